// round 14
// baseline (speedup 1.0000x reference)
#include <cuda_runtime.h>
#include <cuda_bf16.h>
#include <math.h>
#include <stdint.h>

// Problem constants
#define BATCH   2048
#define LEN     49
#define CH      384
#define HEADS   12
#define HDIM    32
#define THREEC  1152
#define NTOK    (BATCH*LEN)   // 100352
#define KDIM    384
#define MASKW   64
#define BM_SLICE 2432         // padded 49*49=2401 -> 16B-aligned slices

// Scratch (device globals — no allocations allowed)
__device__ __nv_bfloat16 g_qkv_hi[NTOK * THREEC], g_qkv_lo[NTOK * THREEC];
__device__ float g_bm[MASKW * HEADS * BM_SLICE + 16];
__device__ __nv_bfloat16 g_x_hi[NTOK * CH],  g_x_lo[NTOK * CH];
__device__ __nv_bfloat16 g_ao_hi[NTOK * CH], g_ao_lo[NTOK * CH];
__device__ __nv_bfloat16 g_wq_hi[THREEC * KDIM], g_wq_lo[THREEC * KDIM]; // [N][K]
__device__ __nv_bfloat16 g_wp_hi[CH * KDIM],     g_wp_lo[CH * KDIM];     // [N][K]

// ---------------------------------------------------------------------------
// Helpers
// ---------------------------------------------------------------------------
__device__ __forceinline__ void cp_async16(void* smem_ptr, const void* gmem_ptr) {
    uint32_t s = (uint32_t)__cvta_generic_to_shared(smem_ptr);
    asm volatile("cp.async.cg.shared.global [%0], [%1], 16;\n"
                 :: "r"(s), "l"(gmem_ptr) : "memory");
}
__device__ __forceinline__ void cp_async_commit() {
    asm volatile("cp.async.commit_group;\n" ::: "memory");
}
template<int N> __device__ __forceinline__ void cp_async_wait_n() {
    asm volatile("cp.async.wait_group %0;\n" :: "n"(N) : "memory");
}
__device__ __forceinline__ void cp_async_wait1() {
    asm volatile("cp.async.wait_group 1;\n" ::: "memory");
}
__device__ __forceinline__ void cp_async_wait0() {
    asm volatile("cp.async.wait_group 0;\n" ::: "memory");
}

#define MMA_BF16(d, a, b)                                                     \
    asm volatile("mma.sync.aligned.m16n8k16.row.col.f32.bf16.bf16.f32 "       \
                 "{%0,%1,%2,%3}, {%4,%5,%6,%7}, {%8,%9}, {%0,%1,%2,%3};\n"    \
                 : "+f"(d[0]), "+f"(d[1]), "+f"(d[2]), "+f"(d[3])             \
                 : "r"(a[0]), "r"(a[1]), "r"(a[2]), "r"(a[3]),                \
                   "r"(b[0]), "r"(b[1]))

#define LDSM_X4(r0, r1, r2, r3, addr)                                         \
    asm volatile("ldmatrix.sync.aligned.m8n8.x4.shared.b16 {%0,%1,%2,%3}, [%4];" \
                 : "=r"(r0), "=r"(r1), "=r"(r2), "=r"(r3) : "r"(addr))

#define LDSM_X4_T(r0, r1, r2, r3, addr)                                       \
    asm volatile("ldmatrix.sync.aligned.m8n8.x4.trans.shared.b16 {%0,%1,%2,%3}, [%4];" \
                 : "=r"(r0), "=r"(r1), "=r"(r2), "=r"(r3) : "r"(addr))

__device__ __forceinline__ uint32_t pack_bf16x2(float a, float b) {
    __nv_bfloat162 p;
    p.x = __float2bfloat16(a);
    p.y = __float2bfloat16(b);
    return *(uint32_t*)&p;
}

// ---------------------------------------------------------------------------
// Pre-pass kernels
// ---------------------------------------------------------------------------
__global__ void bm_kernel(const int* __restrict__ rel_index,
                          const float* __restrict__ table,
                          const float* __restrict__ attn_mask) {
    int idx = blockIdx.x * blockDim.x + threadIdx.x;
    const int total = MASKW * HEADS * LEN * LEN;
    if (idx >= total) return;
    int qk = idx % (LEN * LEN);
    int h  = (idx / (LEN * LEN)) % HEADS;
    int w  = idx / (HEADS * LEN * LEN);
    g_bm[(w * HEADS + h) * BM_SLICE + qk] =
        table[rel_index[qk] * HEADS + h] + attn_mask[w * LEN * LEN + qk];
}

__global__ void split_x_kernel(const float* __restrict__ src, int n4) {
    int i = blockIdx.x * blockDim.x + threadIdx.x;
    if (i >= n4) return;
    float4 v = ((const float4*)src)[i];
    float a[4] = {v.x, v.y, v.z, v.w};
    __nv_bfloat162 h01, h23, l01, l23;
    __nv_bfloat16 hh[4];
    #pragma unroll
    for (int j = 0; j < 4; j++) hh[j] = __float2bfloat16(a[j]);
    h01.x = hh[0]; h01.y = hh[1]; h23.x = hh[2]; h23.y = hh[3];
    l01.x = __float2bfloat16(a[0] - __bfloat162float(hh[0]));
    l01.y = __float2bfloat16(a[1] - __bfloat162float(hh[1]));
    l23.x = __float2bfloat16(a[2] - __bfloat162float(hh[2]));
    l23.y = __float2bfloat16(a[3] - __bfloat162float(hh[3]));
    ((__nv_bfloat162*)g_x_hi)[2*i]   = h01;
    ((__nv_bfloat162*)g_x_hi)[2*i+1] = h23;
    ((__nv_bfloat162*)g_x_lo)[2*i]   = l01;
    ((__nv_bfloat162*)g_x_lo)[2*i+1] = l23;
}

__global__ void wsplit_kernel(const float* __restrict__ w,
                              __nv_bfloat16* __restrict__ hi,
                              __nv_bfloat16* __restrict__ lo, int N) {
    int idx = blockIdx.x * blockDim.x + threadIdx.x;
    if (idx >= N * KDIM) return;
    int n = idx / KDIM, k = idx - n * KDIM;
    float v = w[k * N + n];
    __nv_bfloat16 h = __float2bfloat16(v);
    hi[idx] = h;
    lo[idx] = __float2bfloat16(v - __bfloat162float(h));
}

// ---------------------------------------------------------------------------
// bf16x3 GEMM, ldmatrix frags, 4-stage BK=16 pipeline, 1 sync/stage, 2 CTAs/SM.
// BM=BN=128, 256 threads (8 warps 2x4), warp tile 64x32.
// Smem row stride 24 bf16 (48B: 16B-aligned, LDSM conflict-free).
// ---------------------------------------------------------------------------
#define BK 16
#define BSTRIDE 24
#define TILE_BF16 (128 * BSTRIDE)      // 3072
#define STAGE_BF16 (4 * TILE_BF16)     // 12288
#define NSTAGE 4
#define GEMM_SMEM_BYTES (NSTAGE * STAGE_BF16 * 2)   // 98304

__device__ __forceinline__ void load_stage(
    const __nv_bfloat16* __restrict__ Ahi, const __nv_bfloat16* __restrict__ Alo,
    const __nv_bfloat16* __restrict__ Bhi, const __nv_bfloat16* __restrict__ Blo,
    __nv_bfloat16* st, int rowBase, int colBase, int k0, int tid)
{
    // Per operand tile: 128 rows x 16 cols = 256 16B chunks; 1 chunk/thread.
    const int row = tid >> 1;
    const int c8  = (tid & 1) * 8;
    const int so  = row * BSTRIDE + c8;
    cp_async16(st + so,                 Ahi + (size_t)(rowBase + row) * KDIM + k0 + c8);
    cp_async16(st + TILE_BF16 + so,     Alo + (size_t)(rowBase + row) * KDIM + k0 + c8);
    cp_async16(st + 2 * TILE_BF16 + so, Bhi + (size_t)(colBase + row) * KDIM + k0 + c8);
    cp_async16(st + 3 * TILE_BF16 + so, Blo + (size_t)(colBase + row) * KDIM + k0 + c8);
}

__global__ void __launch_bounds__(256, 2) gemm_bf16x3_kernel(
    const __nv_bfloat16* __restrict__ Ahi, const __nv_bfloat16* __restrict__ Alo,
    const __nv_bfloat16* __restrict__ Bhi, const __nv_bfloat16* __restrict__ Blo,
    const float* __restrict__ bias, float* __restrict__ C,
    __nv_bfloat16* __restrict__ Chi, __nv_bfloat16* __restrict__ Clo, int Ntot)
{
    extern __shared__ __nv_bfloat16 smem[];

    const int tid  = threadIdx.x;
    const int lane = tid & 31;
    const int w    = tid >> 5;
    const int wm   = w >> 2;
    const int wn   = w & 3;
    const int g    = lane >> 3;
    const int li   = lane & 7;
    const int rowBase = blockIdx.y * 128;
    const int colBase = blockIdx.x * 128;
    const uint32_t sb = (uint32_t)__cvta_generic_to_shared(smem);

    float acc[4][4][4];
    #pragma unroll
    for (int i = 0; i < 4; i++)
        #pragma unroll
        for (int j = 0; j < 4; j++)
            #pragma unroll
            for (int r = 0; r < 4; r++) acc[i][j][r] = 0.f;

    const int nStages = KDIM / BK;  // 24

    // Prologue: 3 stages in flight
    load_stage(Ahi, Alo, Bhi, Blo, smem,                  rowBase, colBase, 0,      tid);
    cp_async_commit();
    load_stage(Ahi, Alo, Bhi, Blo, smem + STAGE_BF16,     rowBase, colBase, BK,     tid);
    cp_async_commit();
    load_stage(Ahi, Alo, Bhi, Blo, smem + 2 * STAGE_BF16, rowBase, colBase, 2 * BK, tid);
    cp_async_commit();

    const int a_row_li = li + (g & 1) * 8;
    const int a_col_g  = (g >> 1) * 8;
    const int b_row_li = li + (g >> 1) * 8;
    const int b_col_g  = (g & 1) * 8;

    #pragma unroll 1
    for (int ks = 0; ks < nStages; ks++) {
        cp_async_wait_n<2>();
        __syncthreads();   // all warps done with buf (ks-1)&3; buf ks&3 ready

        const uint32_t st = sb + ((ks & 3) * STAGE_BF16) * 2;
        const uint32_t ah_b = st;
        const uint32_t al_b = st + TILE_BF16 * 2;
        const uint32_t bh_b = st + 2 * TILE_BF16 * 2;
        const uint32_t bl_b = st + 3 * TILE_BF16 * 2;

        uint32_t ah[4][4], al[4][4], bh[2][4], bl[2][4];
        #pragma unroll
        for (int mt = 0; mt < 4; mt++) {
            int arow = wm * 64 + mt * 16 + a_row_li;
            uint32_t aoff = (uint32_t)(arow * BSTRIDE + a_col_g) * 2;
            LDSM_X4(ah[mt][0], ah[mt][1], ah[mt][2], ah[mt][3], ah_b + aoff);
            LDSM_X4(al[mt][0], al[mt][1], al[mt][2], al[mt][3], al_b + aoff);
        }
        #pragma unroll
        for (int np = 0; np < 2; np++) {
            int brow = wn * 32 + np * 16 + b_row_li;
            uint32_t boff = (uint32_t)(brow * BSTRIDE + b_col_g) * 2;
            LDSM_X4(bh[np][0], bh[np][1], bh[np][2], bh[np][3], bh_b + boff);
            LDSM_X4(bl[np][0], bl[np][1], bl[np][2], bl[np][3], bl_b + boff);
        }
        #pragma unroll
        for (int mt = 0; mt < 4; mt++)
            #pragma unroll
            for (int np = 0; np < 2; np++) {
                uint32_t bh0[2] = {bh[np][0], bh[np][1]};
                uint32_t bh1[2] = {bh[np][2], bh[np][3]};
                uint32_t bl0[2] = {bl[np][0], bl[np][1]};
                uint32_t bl1[2] = {bl[np][2], bl[np][3]};
                MMA_BF16(acc[mt][np * 2],     ah[mt], bh0);
                MMA_BF16(acc[mt][np * 2],     ah[mt], bl0);
                MMA_BF16(acc[mt][np * 2],     al[mt], bh0);
                MMA_BF16(acc[mt][np * 2 + 1], ah[mt], bh1);
                MMA_BF16(acc[mt][np * 2 + 1], ah[mt], bl1);
                MMA_BF16(acc[mt][np * 2 + 1], al[mt], bh1);
            }

        if (ks + 3 < nStages) {
            load_stage(Ahi, Alo, Bhi, Blo, smem + ((ks + 3) & 3) * STAGE_BF16,
                       rowBase, colBase, (ks + 3) * BK, tid);
        }
        cp_async_commit();   // always commit to keep wait<2> accounting exact
    }

    // Epilogue
    #pragma unroll
    for (int mt = 0; mt < 4; mt++) {
        int row = rowBase + wm * 64 + mt * 16 + (lane >> 2);
        #pragma unroll
        for (int nt = 0; nt < 4; nt++) {
            int col = colBase + wn * 32 + nt * 8 + (lane & 3) * 2;
            float b0 = bias[col], b1 = bias[col + 1];
            float v00 = acc[mt][nt][0] + b0, v01 = acc[mt][nt][1] + b1;
            float v10 = acc[mt][nt][2] + b0, v11 = acc[mt][nt][3] + b1;
            if (Chi) {
                __nv_bfloat162 h0, h1, l0, l1;
                h0.x = __float2bfloat16(v00); h0.y = __float2bfloat16(v01);
                h1.x = __float2bfloat16(v10); h1.y = __float2bfloat16(v11);
                l0.x = __float2bfloat16(v00 - __bfloat162float(h0.x));
                l0.y = __float2bfloat16(v01 - __bfloat162float(h0.y));
                l1.x = __float2bfloat16(v10 - __bfloat162float(h1.x));
                l1.y = __float2bfloat16(v11 - __bfloat162float(h1.y));
                *(__nv_bfloat162*)&Chi[(size_t)row * Ntot + col]       = h0;
                *(__nv_bfloat162*)&Chi[(size_t)(row + 8) * Ntot + col] = h1;
                *(__nv_bfloat162*)&Clo[(size_t)row * Ntot + col]       = l0;
                *(__nv_bfloat162*)&Clo[(size_t)(row + 8) * Ntot + col] = l1;
            } else {
                *(float2*)&C[(size_t)row * Ntot + col]       = make_float2(v00, v01);
                *(float2*)&C[(size_t)(row + 8) * Ntot + col] = make_float2(v10, v11);
            }
        }
    }
}

// ---------------------------------------------------------------------------
// Tensor-core window attention (bf16x3), FA2 register-P — unchanged from R10.
// ---------------------------------------------------------------------------
#define AQS 40
#define A_BM 15360
#define ATTN_SMEM_BYTES (30720 + BM_SLICE * 4)

__global__ void __launch_bounds__(128) attn_mma_kernel() {
    extern __shared__ __nv_bfloat16 asm_s[];
    float* bm_s = (float*)(asm_s + A_BM);
    const int tid  = threadIdx.x;
    const int lane = tid & 31;
    const int w    = tid >> 5;
    const int h = blockIdx.x;
    const int b = blockIdx.y;
    const float scale = 0.17677669529663687f;   // 1/sqrt(32)

    for (int i = tid; i < 6 * 15 * 20; i += 128) {
        int sel = i / 300;
        int rem = i - sel * 300;
        int r = 49 + rem / 20;
        int c2 = (rem % 20) * 2;
        *(uint32_t*)(asm_s + sel * 2560 + r * AQS + c2) = 0u;
    }
    {
        const __nv_bfloat16* hi = g_qkv_hi + (size_t)b * LEN * THREEC + h * HDIM;
        const __nv_bfloat16* lo = g_qkv_lo + (size_t)b * LEN * THREEC + h * HDIM;
        for (int i = tid; i < 6 * 49 * 4; i += 128) {
            int sel = i / 196;
            int rem = i - sel * 196;
            int r = rem >> 2, c8 = (rem & 3) * 8;
            const __nv_bfloat16* base = (sel & 1) ? lo : hi;
            cp_async16(asm_s + sel * 2560 + r * AQS + c8,
                       base + (size_t)r * THREEC + (sel >> 1) * CH + c8);
        }
    }
    cp_async_commit();
    {
        const float* bm_g = g_bm + (size_t)((b & 63) * HEADS + h) * BM_SLICE;
        for (int i = tid; i < BM_SLICE / 4; i += 128)
            cp_async16(bm_s + i * 4, bm_g + i * 4);
    }
    cp_async_commit();
    cp_async_wait1();
    __syncthreads();

    const uint32_t sb = (uint32_t)__cvta_generic_to_shared(asm_s);
    const int g = lane >> 3;
    const int li = lane & 7;

    float acc[8][4];
    #pragma unroll
    for (int nt = 0; nt < 8; nt++)
        #pragma unroll
        for (int r = 0; r < 4; r++) acc[nt][r] = 0.f;

    #pragma unroll
    for (int ks = 0; ks < 2; ks++) {
        int arow = 16 * w + li + (g & 1) * 8;
        int acol = ks * 16 + (g >> 1) * 8;
        uint32_t aaddr_off = (uint32_t)(arow * AQS + acol) * 2;
        uint32_t qh_[4], ql_[4];
        LDSM_X4(qh_[0], qh_[1], qh_[2], qh_[3], sb + 0 * 2560 * 2 + aaddr_off);
        LDSM_X4(ql_[0], ql_[1], ql_[2], ql_[3], sb + 1 * 2560 * 2 + aaddr_off);

        #pragma unroll
        for (int np = 0; np < 4; np++) {
            int brow = np * 16 + li + (g >> 1) * 8;
            int bcol = ks * 16 + (g & 1) * 8;
            uint32_t baddr_off = (uint32_t)(brow * AQS + bcol) * 2;
            uint32_t kh_[4], kl_[4];
            LDSM_X4(kh_[0], kh_[1], kh_[2], kh_[3], sb + 2 * 2560 * 2 + baddr_off);
            LDSM_X4(kl_[0], kl_[1], kl_[2], kl_[3], sb + 3 * 2560 * 2 + baddr_off);
            uint32_t bh0[2] = {kh_[0], kh_[1]}, bh1[2] = {kh_[2], kh_[3]};
            uint32_t bl0[2] = {kl_[0], kl_[1]}, bl1[2] = {kl_[2], kl_[3]};
            MMA_BF16(acc[np * 2],     qh_, bh0);
            MMA_BF16(acc[np * 2],     qh_, bl0);
            MMA_BF16(acc[np * 2],     ql_, bh0);
            MMA_BF16(acc[np * 2 + 1], qh_, bh1);
            MMA_BF16(acc[np * 2 + 1], qh_, bl1);
            MMA_BF16(acc[np * 2 + 1], ql_, bh1);
        }
    }

    cp_async_wait0();
    __syncthreads();

    const int qi0 = 16 * w + (lane >> 2);
    const int qi1 = qi0 + 8;
    #pragma unroll
    for (int nt = 0; nt < 8; nt++) {
        int kj = nt * 8 + (lane & 3) * 2;
        #pragma unroll
        for (int e = 0; e < 2; e++) {
            int col = kj + e;
            float bm0 = 0.f, bm1 = 0.f;
            if (col < LEN) {
                if (qi0 < LEN) bm0 = bm_s[qi0 * LEN + col];
                if (qi1 < LEN) bm1 = bm_s[qi1 * LEN + col];
            } else { bm0 = -1e30f; bm1 = -1e30f; }
            acc[nt][e]     = fmaf(acc[nt][e],     scale, bm0);
            acc[nt][e + 2] = fmaf(acc[nt][e + 2], scale, bm1);
        }
    }

    float m0 = -1e30f, m1 = -1e30f;
    #pragma unroll
    for (int nt = 0; nt < 8; nt++) {
        m0 = fmaxf(m0, fmaxf(acc[nt][0], acc[nt][1]));
        m1 = fmaxf(m1, fmaxf(acc[nt][2], acc[nt][3]));
    }
    m0 = fmaxf(m0, __shfl_xor_sync(0xffffffffu, m0, 1));
    m0 = fmaxf(m0, __shfl_xor_sync(0xffffffffu, m0, 2));
    m1 = fmaxf(m1, __shfl_xor_sync(0xffffffffu, m1, 1));
    m1 = fmaxf(m1, __shfl_xor_sync(0xffffffffu, m1, 2));
    float s0 = 0.f, s1 = 0.f;
    #pragma unroll
    for (int nt = 0; nt < 8; nt++) {
        acc[nt][0] = __expf(acc[nt][0] - m0);
        acc[nt][1] = __expf(acc[nt][1] - m0);
        acc[nt][2] = __expf(acc[nt][2] - m1);
        acc[nt][3] = __expf(acc[nt][3] - m1);
        s0 += acc[nt][0] + acc[nt][1];
        s1 += acc[nt][2] + acc[nt][3];
    }
    s0 += __shfl_xor_sync(0xffffffffu, s0, 1);
    s0 += __shfl_xor_sync(0xffffffffu, s0, 2);
    s1 += __shfl_xor_sync(0xffffffffu, s1, 1);
    s1 += __shfl_xor_sync(0xffffffffu, s1, 2);
    float i0 = 1.f / s0, i1 = 1.f / s1;

    float oacc[4][4];
    #pragma unroll
    for (int nt = 0; nt < 4; nt++)
        #pragma unroll
        for (int r = 0; r < 4; r++) oacc[nt][r] = 0.f;

    #pragma unroll
    for (int ks = 0; ks < 4; ks++) {
        float p00 = acc[2*ks][0]   * i0, p01 = acc[2*ks][1]   * i0;
        float p02 = acc[2*ks][2]   * i1, p03 = acc[2*ks][3]   * i1;
        float p10 = acc[2*ks+1][0] * i0, p11 = acc[2*ks+1][1] * i0;
        float p12 = acc[2*ks+1][2] * i1, p13 = acc[2*ks+1][3] * i1;

        uint32_t ph_[4], pl_[4];
        ph_[0] = pack_bf16x2(p00, p01);
        ph_[1] = pack_bf16x2(p02, p03);
        ph_[2] = pack_bf16x2(p10, p11);
        ph_[3] = pack_bf16x2(p12, p13);
        {
            __nv_bfloat162 hh;
            *(uint32_t*)&hh = ph_[0];
            pl_[0] = pack_bf16x2(p00 - __bfloat162float(hh.x), p01 - __bfloat162float(hh.y));
            *(uint32_t*)&hh = ph_[1];
            pl_[1] = pack_bf16x2(p02 - __bfloat162float(hh.x), p03 - __bfloat162float(hh.y));
            *(uint32_t*)&hh = ph_[2];
            pl_[2] = pack_bf16x2(p10 - __bfloat162float(hh.x), p11 - __bfloat162float(hh.y));
            *(uint32_t*)&hh = ph_[3];
            pl_[3] = pack_bf16x2(p12 - __bfloat162float(hh.x), p13 - __bfloat162float(hh.y));
        }

        #pragma unroll
        for (int dp = 0; dp < 2; dp++) {
            int vrow = ks * 16 + li + (g & 1) * 8;
            int vcol = dp * 16 + (g >> 1) * 8;
            uint32_t voff = (uint32_t)(vrow * AQS + vcol) * 2;
            uint32_t vh_[4], vl_[4];
            LDSM_X4_T(vh_[0], vh_[1], vh_[2], vh_[3], sb + 4 * 2560 * 2 + voff);
            LDSM_X4_T(vl_[0], vl_[1], vl_[2], vl_[3], sb + 5 * 2560 * 2 + voff);
            uint32_t bh0[2] = {vh_[0], vh_[1]}, bh1[2] = {vh_[2], vh_[3]};
            uint32_t bl0[2] = {vl_[0], vl_[1]}, bl1[2] = {vl_[2], vl_[3]};
            MMA_BF16(oacc[dp * 2],     ph_, bh0);
            MMA_BF16(oacc[dp * 2],     ph_, bl0);
            MMA_BF16(oacc[dp * 2],     pl_, bh0);
            MMA_BF16(oacc[dp * 2 + 1], ph_, bh1);
            MMA_BF16(oacc[dp * 2 + 1], ph_, bl1);
            MMA_BF16(oacc[dp * 2 + 1], pl_, bh1);
        }
    }

    #pragma unroll
    for (int nt = 0; nt < 4; nt++) {
        int d = nt * 8 + (lane & 3) * 2;
        #pragma unroll
        for (int rr = 0; rr < 2; rr++) {
            int qi = (rr == 0) ? qi0 : qi1;
            if (qi < LEN) {
                float v0 = oacc[nt][rr * 2], v1 = oacc[nt][rr * 2 + 1];
                __nv_bfloat162 hh, ll;
                hh.x = __float2bfloat16(v0); hh.y = __float2bfloat16(v1);
                ll.x = __float2bfloat16(v0 - __bfloat162float(hh.x));
                ll.y = __float2bfloat16(v1 - __bfloat162float(hh.y));
                size_t off = ((size_t)b * LEN + qi) * CH + h * HDIM + d;
                *(__nv_bfloat162*)(g_ao_hi + off) = hh;
                *(__nv_bfloat162*)(g_ao_lo + off) = ll;
            }
        }
    }
}

// ---------------------------------------------------------------------------
// Launch
// ---------------------------------------------------------------------------
extern "C" void kernel_launch(void* const* d_in, const int* in_sizes, int n_in,
                              void* d_out, int out_size) {
    const float* x          = (const float*)d_in[0];
    const int*   rel_index  = (const int*)d_in[1];
    const float* attn_mask  = (const float*)d_in[2];
    const float* qkv_w      = (const float*)d_in[3];
    const float* qkv_b      = (const float*)d_in[4];
    const float* bias_table = (const float*)d_in[5];
    const float* proj_w     = (const float*)d_in[6];
    const float* proj_b     = (const float*)d_in[7];
    float* out = (float*)d_out;

    __nv_bfloat16 *qkvh, *qkvl, *xh, *xl, *aoh, *aol, *wqh, *wql, *wph, *wpl;
    cudaGetSymbolAddress((void**)&qkvh, g_qkv_hi);
    cudaGetSymbolAddress((void**)&qkvl, g_qkv_lo);
    cudaGetSymbolAddress((void**)&xh,  g_x_hi);
    cudaGetSymbolAddress((void**)&xl,  g_x_lo);
    cudaGetSymbolAddress((void**)&aoh, g_ao_hi);
    cudaGetSymbolAddress((void**)&aol, g_ao_lo);
    cudaGetSymbolAddress((void**)&wqh, g_wq_hi);
    cudaGetSymbolAddress((void**)&wql, g_wq_lo);
    cudaGetSymbolAddress((void**)&wph, g_wp_hi);
    cudaGetSymbolAddress((void**)&wpl, g_wp_lo);

    cudaFuncSetAttribute(gemm_bf16x3_kernel,
                         cudaFuncAttributeMaxDynamicSharedMemorySize,
                         GEMM_SMEM_BYTES);
    cudaFuncSetAttribute(attn_mma_kernel,
                         cudaFuncAttributeMaxDynamicSharedMemorySize,
                         ATTN_SMEM_BYTES);

    // 1) combined bias+mask table
    {
        int total = MASKW * HEADS * LEN * LEN;
        bm_kernel<<<(total + 255) / 256, 256>>>(rel_index, bias_table, attn_mask);
    }
    // 2) split x -> bf16 hi/lo
    {
        int n4 = NTOK * CH / 4;
        split_x_kernel<<<(n4 + 255) / 256, 256>>>(x, n4);
    }
    // 3) weight transpose+split
    {
        int nq = THREEC * KDIM;
        wsplit_kernel<<<(nq + 255) / 256, 256>>>(qkv_w, wqh, wql, THREEC);
        int np = CH * KDIM;
        wsplit_kernel<<<(np + 255) / 256, 256>>>(proj_w, wph, wpl, CH);
    }
    // 4) qkv GEMM -> split bf16 output
    {
        dim3 grid(THREEC / 128, NTOK / 128);
        gemm_bf16x3_kernel<<<grid, 256, GEMM_SMEM_BYTES>>>(
            xh, xl, wqh, wql, qkv_b, nullptr, qkvh, qkvl, THREEC);
    }
    // 5) attention (tensor-core, register-P)
    {
        dim3 grid(HEADS, BATCH);
        attn_mma_kernel<<<grid, 128, ATTN_SMEM_BYTES>>>();
    }
    // 6) proj GEMM -> fp32 out
    {
        dim3 grid(CH / 128, NTOK / 128);
        gemm_bf16x3_kernel<<<grid, 256, GEMM_SMEM_BYTES>>>(
            aoh, aol, wph, wpl, proj_b, out, nullptr, nullptr, CH);
    }
}

// round 15
// speedup vs baseline: 1.4774x; 1.4774x over previous
#include <cuda_runtime.h>
#include <cuda_bf16.h>
#include <math.h>
#include <stdint.h>

// Problem constants
#define BATCH   2048
#define LEN     49
#define CH      384
#define HEADS   12
#define HDIM    32
#define THREEC  1152
#define NTOK    (BATCH*LEN)   // 100352
#define KDIM    384
#define MASKW   64
#define BM_SLICE 2432         // padded 49*49 -> 16B-aligned slices

// Scratch (device globals — no allocations allowed)
__device__ __nv_bfloat16 g_qkv_hi[NTOK * THREEC], g_qkv_lo[NTOK * THREEC];
__device__ float g_bm[MASKW * HEADS * BM_SLICE + 16];
__device__ __nv_bfloat16 g_x_hi[NTOK * CH],  g_x_lo[NTOK * CH];
__device__ __nv_bfloat16 g_ao_hi[NTOK * CH], g_ao_lo[NTOK * CH];
__device__ __nv_bfloat16 g_wq_hi[THREEC * KDIM], g_wq_lo[THREEC * KDIM]; // [N][K]
__device__ __nv_bfloat16 g_wp_hi[CH * KDIM],     g_wp_lo[CH * KDIM];     // [N][K]

// ---------------------------------------------------------------------------
// Helpers
// ---------------------------------------------------------------------------
__device__ __forceinline__ void cp_async16(void* smem_ptr, const void* gmem_ptr) {
    uint32_t s = (uint32_t)__cvta_generic_to_shared(smem_ptr);
    asm volatile("cp.async.cg.shared.global [%0], [%1], 16;\n"
                 :: "r"(s), "l"(gmem_ptr) : "memory");
}
__device__ __forceinline__ void cp_async_commit() {
    asm volatile("cp.async.commit_group;\n" ::: "memory");
}
__device__ __forceinline__ void cp_async_wait1() {
    asm volatile("cp.async.wait_group 1;\n" ::: "memory");
}
__device__ __forceinline__ void cp_async_wait0() {
    asm volatile("cp.async.wait_group 0;\n" ::: "memory");
}

#define MMA_BF16(d, a, b)                                                     \
    asm volatile("mma.sync.aligned.m16n8k16.row.col.f32.bf16.bf16.f32 "       \
                 "{%0,%1,%2,%3}, {%4,%5,%6,%7}, {%8,%9}, {%0,%1,%2,%3};\n"    \
                 : "+f"(d[0]), "+f"(d[1]), "+f"(d[2]), "+f"(d[3])             \
                 : "r"(a[0]), "r"(a[1]), "r"(a[2]), "r"(a[3]),                \
                   "r"(b[0]), "r"(b[1]))

#define LDSM_X4(r0, r1, r2, r3, addr)                                         \
    asm volatile("ldmatrix.sync.aligned.m8n8.x4.shared.b16 {%0,%1,%2,%3}, [%4];" \
                 : "=r"(r0), "=r"(r1), "=r"(r2), "=r"(r3) : "r"(addr))

#define LDSM_X4_T(r0, r1, r2, r3, addr)                                       \
    asm volatile("ldmatrix.sync.aligned.m8n8.x4.trans.shared.b16 {%0,%1,%2,%3}, [%4];" \
                 : "=r"(r0), "=r"(r1), "=r"(r2), "=r"(r3) : "r"(addr))

__device__ __forceinline__ uint32_t pack_bf16x2(float a, float b) {
    __nv_bfloat162 p;
    p.x = __float2bfloat16(a);
    p.y = __float2bfloat16(b);
    return *(uint32_t*)&p;
}

// ---------------------------------------------------------------------------
// Pre-pass kernels
// ---------------------------------------------------------------------------
__global__ void bm_kernel(const int* __restrict__ rel_index,
                          const float* __restrict__ table,
                          const float* __restrict__ attn_mask) {
    int idx = blockIdx.x * blockDim.x + threadIdx.x;
    const int total = MASKW * HEADS * LEN * LEN;
    if (idx >= total) return;
    int qk = idx % (LEN * LEN);
    int h  = (idx / (LEN * LEN)) % HEADS;
    int w  = idx / (HEADS * LEN * LEN);
    g_bm[(w * HEADS + h) * BM_SLICE + qk] =
        table[rel_index[qk] * HEADS + h] + attn_mask[w * LEN * LEN + qk];
}

__global__ void split_x_kernel(const float* __restrict__ src, int n4) {
    int i = blockIdx.x * blockDim.x + threadIdx.x;
    if (i >= n4) return;
    float4 v = ((const float4*)src)[i];
    float a[4] = {v.x, v.y, v.z, v.w};
    __nv_bfloat162 h01, h23, l01, l23;
    __nv_bfloat16 hh[4];
    #pragma unroll
    for (int j = 0; j < 4; j++) hh[j] = __float2bfloat16(a[j]);
    h01.x = hh[0]; h01.y = hh[1]; h23.x = hh[2]; h23.y = hh[3];
    l01.x = __float2bfloat16(a[0] - __bfloat162float(hh[0]));
    l01.y = __float2bfloat16(a[1] - __bfloat162float(hh[1]));
    l23.x = __float2bfloat16(a[2] - __bfloat162float(hh[2]));
    l23.y = __float2bfloat16(a[3] - __bfloat162float(hh[3]));
    ((__nv_bfloat162*)g_x_hi)[2*i]   = h01;
    ((__nv_bfloat162*)g_x_hi)[2*i+1] = h23;
    ((__nv_bfloat162*)g_x_lo)[2*i]   = l01;
    ((__nv_bfloat162*)g_x_lo)[2*i+1] = l23;
}

// Both weight matrices in one launch: idx < THREEC*KDIM -> qkv_w, else proj_w
__global__ void wsplit_all_kernel(const float* __restrict__ wq,
                                  const float* __restrict__ wp) {
    int idx = blockIdx.x * blockDim.x + threadIdx.x;
    const int nq = THREEC * KDIM;
    const int np = CH * KDIM;
    if (idx < nq) {
        int n = idx / KDIM, k = idx - n * KDIM;
        float v = wq[k * THREEC + n];
        __nv_bfloat16 h = __float2bfloat16(v);
        g_wq_hi[idx] = h;
        g_wq_lo[idx] = __float2bfloat16(v - __bfloat162float(h));
    } else if (idx < nq + np) {
        int j = idx - nq;
        int n = j / KDIM, k = j - n * KDIM;
        float v = wp[k * CH + n];
        __nv_bfloat16 h = __float2bfloat16(v);
        g_wp_hi[j] = h;
        g_wp_lo[j] = __float2bfloat16(v - __bfloat162float(h));
    }
}

// ---------------------------------------------------------------------------
// bf16x3 GEMM — exact R11 config: ldmatrix frags, 2-stage BK=32, 2 CTAs/SM.
// BM=BN=128, 256 threads (8 warps 2x4), warp tile 64x32, stride 40.
// ---------------------------------------------------------------------------
#define BSTRIDE 40
#define TILE_BF16 (128 * BSTRIDE)
#define STAGE_BF16 (4 * TILE_BF16)
#define GEMM_SMEM_BYTES (2 * STAGE_BF16 * 2)   // 81920

__device__ __forceinline__ void load_stage(
    const __nv_bfloat16* __restrict__ Ahi, const __nv_bfloat16* __restrict__ Alo,
    const __nv_bfloat16* __restrict__ Bhi, const __nv_bfloat16* __restrict__ Blo,
    __nv_bfloat16* st, int rowBase, int colBase, int k0, int tid)
{
    #pragma unroll
    for (int i = 0; i < 8; i++) {
        const int sel = i >> 1;
        int j   = tid + 256 * (i & 1);
        int row = j >> 2;
        int c8  = (j & 3) * 8;
        __nv_bfloat16* dst = st + sel * TILE_BF16 + row * BSTRIDE + c8;
        const __nv_bfloat16* src;
        if      (sel == 0) src = Ahi + (size_t)(rowBase + row) * KDIM + k0 + c8;
        else if (sel == 1) src = Alo + (size_t)(rowBase + row) * KDIM + k0 + c8;
        else if (sel == 2) src = Bhi + (size_t)(colBase + row) * KDIM + k0 + c8;
        else               src = Blo + (size_t)(colBase + row) * KDIM + k0 + c8;
        cp_async16(dst, src);
    }
}

__global__ void __launch_bounds__(256, 2) gemm_bf16x3_kernel(
    const __nv_bfloat16* __restrict__ Ahi, const __nv_bfloat16* __restrict__ Alo,
    const __nv_bfloat16* __restrict__ Bhi, const __nv_bfloat16* __restrict__ Blo,
    const float* __restrict__ bias, float* __restrict__ C,
    __nv_bfloat16* __restrict__ Chi, __nv_bfloat16* __restrict__ Clo, int Ntot)
{
    extern __shared__ __nv_bfloat16 smem[];

    const int tid  = threadIdx.x;
    const int lane = tid & 31;
    const int w    = tid >> 5;
    const int wm   = w >> 2;
    const int wn   = w & 3;
    const int g    = lane >> 3;
    const int li   = lane & 7;
    const int rowBase = blockIdx.y * 128;
    const int colBase = blockIdx.x * 128;
    const uint32_t sb = (uint32_t)__cvta_generic_to_shared(smem);

    float acc[4][4][4];
    #pragma unroll
    for (int i = 0; i < 4; i++)
        #pragma unroll
        for (int j = 0; j < 4; j++)
            #pragma unroll
            for (int r = 0; r < 4; r++) acc[i][j][r] = 0.f;

    const int nStages = KDIM / 32;  // 12

    load_stage(Ahi, Alo, Bhi, Blo, smem,              rowBase, colBase, 0,  tid);
    cp_async_commit();
    load_stage(Ahi, Alo, Bhi, Blo, smem + STAGE_BF16, rowBase, colBase, 32, tid);
    cp_async_commit();

    const int a_row_li = li + (g & 1) * 8;
    const int a_col_g  = (g >> 1) * 8;
    const int b_row_li = li + (g >> 1) * 8;
    const int b_col_g  = (g & 1) * 8;

    #pragma unroll 1
    for (int ks = 0; ks < nStages; ks++) {
        cp_async_wait1();
        __syncthreads();

        const uint32_t st = sb + ((ks & 1) * STAGE_BF16) * 2;
        const uint32_t ah_b = st;
        const uint32_t al_b = st + TILE_BF16 * 2;
        const uint32_t bh_b = st + 2 * TILE_BF16 * 2;
        const uint32_t bl_b = st + 3 * TILE_BF16 * 2;

        #pragma unroll
        for (int kk = 0; kk < 2; kk++) {
            const int acol = kk * 16 + a_col_g;
            const int bcol = kk * 16 + b_col_g;
            uint32_t ah[4][4], al[4][4], bh[2][4], bl[2][4];
            #pragma unroll
            for (int mt = 0; mt < 4; mt++) {
                int arow = wm * 64 + mt * 16 + a_row_li;
                uint32_t aoff = (uint32_t)(arow * BSTRIDE + acol) * 2;
                LDSM_X4(ah[mt][0], ah[mt][1], ah[mt][2], ah[mt][3], ah_b + aoff);
                LDSM_X4(al[mt][0], al[mt][1], al[mt][2], al[mt][3], al_b + aoff);
            }
            #pragma unroll
            for (int np = 0; np < 2; np++) {
                int brow = wn * 32 + np * 16 + b_row_li;
                uint32_t boff = (uint32_t)(brow * BSTRIDE + bcol) * 2;
                LDSM_X4(bh[np][0], bh[np][1], bh[np][2], bh[np][3], bh_b + boff);
                LDSM_X4(bl[np][0], bl[np][1], bl[np][2], bl[np][3], bl_b + boff);
            }
            #pragma unroll
            for (int mt = 0; mt < 4; mt++)
                #pragma unroll
                for (int np = 0; np < 2; np++) {
                    uint32_t bh0[2] = {bh[np][0], bh[np][1]};
                    uint32_t bh1[2] = {bh[np][2], bh[np][3]};
                    uint32_t bl0[2] = {bl[np][0], bl[np][1]};
                    uint32_t bl1[2] = {bl[np][2], bl[np][3]};
                    MMA_BF16(acc[mt][np * 2],     ah[mt], bh0);
                    MMA_BF16(acc[mt][np * 2],     ah[mt], bl0);
                    MMA_BF16(acc[mt][np * 2],     al[mt], bh0);
                    MMA_BF16(acc[mt][np * 2 + 1], ah[mt], bh1);
                    MMA_BF16(acc[mt][np * 2 + 1], ah[mt], bl1);
                    MMA_BF16(acc[mt][np * 2 + 1], al[mt], bh1);
                }
        }
        __syncthreads();
        if (ks + 2 < nStages) {
            load_stage(Ahi, Alo, Bhi, Blo, smem + (ks & 1) * STAGE_BF16,
                       rowBase, colBase, (ks + 2) * 32, tid);
        }
        cp_async_commit();
    }

    // Epilogue
    #pragma unroll
    for (int mt = 0; mt < 4; mt++) {
        int row = rowBase + wm * 64 + mt * 16 + (lane >> 2);
        #pragma unroll
        for (int nt = 0; nt < 4; nt++) {
            int col = colBase + wn * 32 + nt * 8 + (lane & 3) * 2;
            float b0 = bias[col], b1 = bias[col + 1];
            float v00 = acc[mt][nt][0] + b0, v01 = acc[mt][nt][1] + b1;
            float v10 = acc[mt][nt][2] + b0, v11 = acc[mt][nt][3] + b1;
            if (Chi) {
                __nv_bfloat162 h0, h1, l0, l1;
                h0.x = __float2bfloat16(v00); h0.y = __float2bfloat16(v01);
                h1.x = __float2bfloat16(v10); h1.y = __float2bfloat16(v11);
                l0.x = __float2bfloat16(v00 - __bfloat162float(h0.x));
                l0.y = __float2bfloat16(v01 - __bfloat162float(h0.y));
                l1.x = __float2bfloat16(v10 - __bfloat162float(h1.x));
                l1.y = __float2bfloat16(v11 - __bfloat162float(h1.y));
                *(__nv_bfloat162*)&Chi[(size_t)row * Ntot + col]       = h0;
                *(__nv_bfloat162*)&Chi[(size_t)(row + 8) * Ntot + col] = h1;
                *(__nv_bfloat162*)&Clo[(size_t)row * Ntot + col]       = l0;
                *(__nv_bfloat162*)&Clo[(size_t)(row + 8) * Ntot + col] = l1;
            } else {
                *(float2*)&C[(size_t)row * Ntot + col]       = make_float2(v00, v01);
                *(float2*)&C[(size_t)(row + 8) * Ntot + col] = make_float2(v10, v11);
            }
        }
    }
}

// ---------------------------------------------------------------------------
// Tensor-core window attention (bf16x3, FA2 register-P), TWO windows/block.
// 256 threads: warps 0-3 -> window b, warps 4-7 -> window b+1024 (same bm
// slice since (b+1024)&63 == b&63).
// Smem: window w at w*15360 bf16 (6 regions x 2560, stride 40);
// bm floats at 30720 (BM_SLICE*4 = 9728 B). Total 71168 B.
// ---------------------------------------------------------------------------
#define AQS 40
#define WIN_BF16 15360
#define A_BM 30720
#define ATTN_SMEM_BYTES (2 * WIN_BF16 * 2 + BM_SLICE * 4)   // 71168

__global__ void __launch_bounds__(256) attn_mma_kernel() {
    extern __shared__ __nv_bfloat16 asm_s[];
    float* bm_s = (float*)(asm_s + A_BM);
    const int tid  = threadIdx.x;
    const int lane = tid & 31;
    const int w    = tid >> 5;        // 0..7
    const int win  = w >> 2;          // 0..1 (this warp's window)
    const int wl   = w & 3;           // warp-in-window
    const int h = blockIdx.x;
    const int b = blockIdx.y + win * 1024;
    const float scale = 0.17677669529663687f;   // 1/sqrt(32)

    // Zero pad rows 49..63 in 2 windows x 6 regions (cols 0..39)
    for (int i = tid; i < 2 * 6 * 15 * 20; i += 256) {
        int wi  = i / 1800;
        int rem = i - wi * 1800;
        int sel = rem / 300;
        int r2  = rem - sel * 300;
        int r = 49 + r2 / 20;
        int c2 = (r2 % 20) * 2;
        *(uint32_t*)(asm_s + wi * WIN_BF16 + sel * 2560 + r * AQS + c2) = 0u;
    }
    // cp.async pre-split Q,K,V for both windows (rows 0..48) — group 1
    for (int i = tid; i < 2 * 6 * 49 * 4; i += 256) {
        int wi  = i / 1176;
        int rem = i - wi * 1176;
        int sel = rem / 196;          // 0..5: qh,ql,kh,kl,vh,vl
        int r2  = rem - sel * 196;
        int r = r2 >> 2, c8 = (r2 & 3) * 8;
        int bw = blockIdx.y + wi * 1024;
        const __nv_bfloat16* base = (sel & 1) ? g_qkv_lo : g_qkv_hi;
        cp_async16(asm_s + wi * WIN_BF16 + sel * 2560 + r * AQS + c8,
                   base + (size_t)bw * LEN * THREEC + h * HDIM
                        + (size_t)r * THREEC + (sel >> 1) * CH + c8);
    }
    cp_async_commit();
    // cp.async shared bias+mask slice — group 2
    {
        const float* bm_g = g_bm + (size_t)((blockIdx.y & 63) * HEADS + h) * BM_SLICE;
        for (int i = tid; i < BM_SLICE / 4; i += 256)
            cp_async16(bm_s + i * 4, bm_g + i * 4);
    }
    cp_async_commit();
    cp_async_wait1();     // QKV ready; bm in flight behind S MMAs
    __syncthreads();

    const uint32_t sb = (uint32_t)__cvta_generic_to_shared(asm_s) + win * WIN_BF16 * 2;
    const int g = lane >> 3;
    const int li = lane & 7;

    // --- S = Q K^T (bf16x3) ---
    float acc[8][4];
    #pragma unroll
    for (int nt = 0; nt < 8; nt++)
        #pragma unroll
        for (int r = 0; r < 4; r++) acc[nt][r] = 0.f;

    #pragma unroll
    for (int ks = 0; ks < 2; ks++) {
        int arow = 16 * wl + li + (g & 1) * 8;
        int acol = ks * 16 + (g >> 1) * 8;
        uint32_t aaddr_off = (uint32_t)(arow * AQS + acol) * 2;
        uint32_t qh_[4], ql_[4];
        LDSM_X4(qh_[0], qh_[1], qh_[2], qh_[3], sb + 0 * 2560 * 2 + aaddr_off);
        LDSM_X4(ql_[0], ql_[1], ql_[2], ql_[3], sb + 1 * 2560 * 2 + aaddr_off);

        #pragma unroll
        for (int np = 0; np < 4; np++) {
            int brow = np * 16 + li + (g >> 1) * 8;
            int bcol = ks * 16 + (g & 1) * 8;
            uint32_t baddr_off = (uint32_t)(brow * AQS + bcol) * 2;
            uint32_t kh_[4], kl_[4];
            LDSM_X4(kh_[0], kh_[1], kh_[2], kh_[3], sb + 2 * 2560 * 2 + baddr_off);
            LDSM_X4(kl_[0], kl_[1], kl_[2], kl_[3], sb + 3 * 2560 * 2 + baddr_off);
            uint32_t bh0[2] = {kh_[0], kh_[1]}, bh1[2] = {kh_[2], kh_[3]};
            uint32_t bl0[2] = {kl_[0], kl_[1]}, bl1[2] = {kl_[2], kl_[3]};
            MMA_BF16(acc[np * 2],     qh_, bh0);
            MMA_BF16(acc[np * 2],     qh_, bl0);
            MMA_BF16(acc[np * 2],     ql_, bh0);
            MMA_BF16(acc[np * 2 + 1], qh_, bh1);
            MMA_BF16(acc[np * 2 + 1], qh_, bl1);
            MMA_BF16(acc[np * 2 + 1], ql_, bh1);
        }
    }

    // bm ready
    cp_async_wait0();
    __syncthreads();

    // --- scale + bias+mask; padding ---
    const int qi0 = 16 * wl + (lane >> 2);
    const int qi1 = qi0 + 8;
    #pragma unroll
    for (int nt = 0; nt < 8; nt++) {
        int kj = nt * 8 + (lane & 3) * 2;
        #pragma unroll
        for (int e = 0; e < 2; e++) {
            int col = kj + e;
            float bm0 = 0.f, bm1 = 0.f;
            if (col < LEN) {
                if (qi0 < LEN) bm0 = bm_s[qi0 * LEN + col];
                if (qi1 < LEN) bm1 = bm_s[qi1 * LEN + col];
            } else { bm0 = -1e30f; bm1 = -1e30f; }
            acc[nt][e]     = fmaf(acc[nt][e],     scale, bm0);
            acc[nt][e + 2] = fmaf(acc[nt][e + 2], scale, bm1);
        }
    }

    // --- softmax in registers ---
    float m0 = -1e30f, m1 = -1e30f;
    #pragma unroll
    for (int nt = 0; nt < 8; nt++) {
        m0 = fmaxf(m0, fmaxf(acc[nt][0], acc[nt][1]));
        m1 = fmaxf(m1, fmaxf(acc[nt][2], acc[nt][3]));
    }
    m0 = fmaxf(m0, __shfl_xor_sync(0xffffffffu, m0, 1));
    m0 = fmaxf(m0, __shfl_xor_sync(0xffffffffu, m0, 2));
    m1 = fmaxf(m1, __shfl_xor_sync(0xffffffffu, m1, 1));
    m1 = fmaxf(m1, __shfl_xor_sync(0xffffffffu, m1, 2));
    float s0 = 0.f, s1 = 0.f;
    #pragma unroll
    for (int nt = 0; nt < 8; nt++) {
        acc[nt][0] = __expf(acc[nt][0] - m0);
        acc[nt][1] = __expf(acc[nt][1] - m0);
        acc[nt][2] = __expf(acc[nt][2] - m1);
        acc[nt][3] = __expf(acc[nt][3] - m1);
        s0 += acc[nt][0] + acc[nt][1];
        s1 += acc[nt][2] + acc[nt][3];
    }
    s0 += __shfl_xor_sync(0xffffffffu, s0, 1);
    s0 += __shfl_xor_sync(0xffffffffu, s0, 2);
    s1 += __shfl_xor_sync(0xffffffffu, s1, 1);
    s1 += __shfl_xor_sync(0xffffffffu, s1, 2);
    float i0 = 1.f / s0, i1 = 1.f / s1;

    // --- O = P V (bf16x3), P fragments in registers ---
    float oacc[4][4];
    #pragma unroll
    for (int nt = 0; nt < 4; nt++)
        #pragma unroll
        for (int r = 0; r < 4; r++) oacc[nt][r] = 0.f;

    #pragma unroll
    for (int ks = 0; ks < 4; ks++) {
        float p00 = acc[2*ks][0]   * i0, p01 = acc[2*ks][1]   * i0;
        float p02 = acc[2*ks][2]   * i1, p03 = acc[2*ks][3]   * i1;
        float p10 = acc[2*ks+1][0] * i0, p11 = acc[2*ks+1][1] * i0;
        float p12 = acc[2*ks+1][2] * i1, p13 = acc[2*ks+1][3] * i1;

        uint32_t ph_[4], pl_[4];
        ph_[0] = pack_bf16x2(p00, p01);
        ph_[1] = pack_bf16x2(p02, p03);
        ph_[2] = pack_bf16x2(p10, p11);
        ph_[3] = pack_bf16x2(p12, p13);
        {
            __nv_bfloat162 hh;
            *(uint32_t*)&hh = ph_[0];
            pl_[0] = pack_bf16x2(p00 - __bfloat162float(hh.x), p01 - __bfloat162float(hh.y));
            *(uint32_t*)&hh = ph_[1];
            pl_[1] = pack_bf16x2(p02 - __bfloat162float(hh.x), p03 - __bfloat162float(hh.y));
            *(uint32_t*)&hh = ph_[2];
            pl_[2] = pack_bf16x2(p10 - __bfloat162float(hh.x), p11 - __bfloat162float(hh.y));
            *(uint32_t*)&hh = ph_[3];
            pl_[3] = pack_bf16x2(p12 - __bfloat162float(hh.x), p13 - __bfloat162float(hh.y));
        }

        #pragma unroll
        for (int dp = 0; dp < 2; dp++) {
            int vrow = ks * 16 + li + (g & 1) * 8;
            int vcol = dp * 16 + (g >> 1) * 8;
            uint32_t voff = (uint32_t)(vrow * AQS + vcol) * 2;
            uint32_t vh_[4], vl_[4];
            LDSM_X4_T(vh_[0], vh_[1], vh_[2], vh_[3], sb + 4 * 2560 * 2 + voff);
            LDSM_X4_T(vl_[0], vl_[1], vl_[2], vl_[3], sb + 5 * 2560 * 2 + voff);
            uint32_t bh0[2] = {vh_[0], vh_[1]}, bh1[2] = {vh_[2], vh_[3]};
            uint32_t bl0[2] = {vl_[0], vl_[1]}, bl1[2] = {vl_[2], vl_[3]};
            MMA_BF16(oacc[dp * 2],     ph_, bh0);
            MMA_BF16(oacc[dp * 2],     ph_, bl0);
            MMA_BF16(oacc[dp * 2],     pl_, bh0);
            MMA_BF16(oacc[dp * 2 + 1], ph_, bh1);
            MMA_BF16(oacc[dp * 2 + 1], ph_, bl1);
            MMA_BF16(oacc[dp * 2 + 1], pl_, bh1);
        }
    }

    // --- write O split hi/lo ---
    #pragma unroll
    for (int nt = 0; nt < 4; nt++) {
        int d = nt * 8 + (lane & 3) * 2;
        #pragma unroll
        for (int rr = 0; rr < 2; rr++) {
            int qi = (rr == 0) ? qi0 : qi1;
            if (qi < LEN) {
                float v0 = oacc[nt][rr * 2], v1 = oacc[nt][rr * 2 + 1];
                __nv_bfloat162 hh, ll;
                hh.x = __float2bfloat16(v0); hh.y = __float2bfloat16(v1);
                ll.x = __float2bfloat16(v0 - __bfloat162float(hh.x));
                ll.y = __float2bfloat16(v1 - __bfloat162float(hh.y));
                size_t off = ((size_t)b * LEN + qi) * CH + h * HDIM + d;
                *(__nv_bfloat162*)(g_ao_hi + off) = hh;
                *(__nv_bfloat162*)(g_ao_lo + off) = ll;
            }
        }
    }
}

// ---------------------------------------------------------------------------
// Launch
// ---------------------------------------------------------------------------
extern "C" void kernel_launch(void* const* d_in, const int* in_sizes, int n_in,
                              void* d_out, int out_size) {
    const float* x          = (const float*)d_in[0];
    const int*   rel_index  = (const int*)d_in[1];
    const float* attn_mask  = (const float*)d_in[2];
    const float* qkv_w      = (const float*)d_in[3];
    const float* qkv_b      = (const float*)d_in[4];
    const float* bias_table = (const float*)d_in[5];
    const float* proj_w     = (const float*)d_in[6];
    const float* proj_b     = (const float*)d_in[7];
    float* out = (float*)d_out;

    __nv_bfloat16 *qkvh, *qkvl, *xh, *xl, *aoh, *aol, *wqh, *wql, *wph, *wpl;
    cudaGetSymbolAddress((void**)&qkvh, g_qkv_hi);
    cudaGetSymbolAddress((void**)&qkvl, g_qkv_lo);
    cudaGetSymbolAddress((void**)&xh,  g_x_hi);
    cudaGetSymbolAddress((void**)&xl,  g_x_lo);
    cudaGetSymbolAddress((void**)&aoh, g_ao_hi);
    cudaGetSymbolAddress((void**)&aol, g_ao_lo);
    cudaGetSymbolAddress((void**)&wqh, g_wq_hi);
    cudaGetSymbolAddress((void**)&wql, g_wq_lo);
    cudaGetSymbolAddress((void**)&wph, g_wp_hi);
    cudaGetSymbolAddress((void**)&wpl, g_wp_lo);

    cudaFuncSetAttribute(gemm_bf16x3_kernel,
                         cudaFuncAttributeMaxDynamicSharedMemorySize,
                         GEMM_SMEM_BYTES);
    cudaFuncSetAttribute(attn_mma_kernel,
                         cudaFuncAttributeMaxDynamicSharedMemorySize,
                         ATTN_SMEM_BYTES);

    // 1) combined bias+mask table
    {
        int total = MASKW * HEADS * LEN * LEN;
        bm_kernel<<<(total + 255) / 256, 256>>>(rel_index, bias_table, attn_mask);
    }
    // 2) split x -> bf16 hi/lo
    {
        int n4 = NTOK * CH / 4;
        split_x_kernel<<<(n4 + 255) / 256, 256>>>(x, n4);
    }
    // 3) weight transpose+split (both matrices, one launch)
    {
        int total = THREEC * KDIM + CH * KDIM;
        wsplit_all_kernel<<<(total + 255) / 256, 256>>>(qkv_w, proj_w);
    }
    // 4) qkv GEMM -> split bf16 output
    {
        dim3 grid(THREEC / 128, NTOK / 128);
        gemm_bf16x3_kernel<<<grid, 256, GEMM_SMEM_BYTES>>>(
            xh, xl, wqh, wql, qkv_b, nullptr, qkvh, qkvl, THREEC);
    }
    // 5) attention (2 windows per block)
    {
        dim3 grid(HEADS, 1024);
        attn_mma_kernel<<<grid, 256, ATTN_SMEM_BYTES>>>();
    }
    // 6) proj GEMM -> fp32 out
    {
        dim3 grid(CH / 128, NTOK / 128);
        gemm_bf16x3_kernel<<<grid, 256, GEMM_SMEM_BYTES>>>(
            aoh, aol, wph, wpl, proj_b, out, nullptr, nullptr, CH);
    }
}

// round 16
// speedup vs baseline: 1.4985x; 1.0142x over previous
#include <cuda_runtime.h>
#include <cuda_bf16.h>
#include <math.h>
#include <stdint.h>

// Problem constants
#define BATCH   2048
#define LEN     49
#define CH      384
#define HEADS   12
#define HDIM    32
#define THREEC  1152
#define NTOK    (BATCH*LEN)   // 100352
#define KDIM    384
#define MASKW   64
#define BM_SLICE 2432         // padded 49*49 -> 16B-aligned slices

// Scratch (device globals — no allocations allowed)
__device__ __nv_bfloat16 g_qkv_hi[NTOK * THREEC], g_qkv_lo[NTOK * THREEC];
__device__ float g_bm[MASKW * HEADS * BM_SLICE + 16];
__device__ __nv_bfloat16 g_x_hi[NTOK * CH],  g_x_lo[NTOK * CH];
__device__ __nv_bfloat16 g_ao_hi[NTOK * CH], g_ao_lo[NTOK * CH];
__device__ __nv_bfloat16 g_wq_hi[THREEC * KDIM], g_wq_lo[THREEC * KDIM]; // [N][K]
__device__ __nv_bfloat16 g_wp_hi[CH * KDIM],     g_wp_lo[CH * KDIM];     // [N][K]

// ---------------------------------------------------------------------------
// Helpers
// ---------------------------------------------------------------------------
__device__ __forceinline__ void cp_async16(void* smem_ptr, const void* gmem_ptr) {
    uint32_t s = (uint32_t)__cvta_generic_to_shared(smem_ptr);
    asm volatile("cp.async.cg.shared.global [%0], [%1], 16;\n"
                 :: "r"(s), "l"(gmem_ptr) : "memory");
}
__device__ __forceinline__ void cp_async_commit() {
    asm volatile("cp.async.commit_group;\n" ::: "memory");
}
__device__ __forceinline__ void cp_async_wait1() {
    asm volatile("cp.async.wait_group 1;\n" ::: "memory");
}
__device__ __forceinline__ void cp_async_wait0() {
    asm volatile("cp.async.wait_group 0;\n" ::: "memory");
}

#define MMA_BF16(d, a, b)                                                     \
    asm volatile("mma.sync.aligned.m16n8k16.row.col.f32.bf16.bf16.f32 "       \
                 "{%0,%1,%2,%3}, {%4,%5,%6,%7}, {%8,%9}, {%0,%1,%2,%3};\n"    \
                 : "+f"(d[0]), "+f"(d[1]), "+f"(d[2]), "+f"(d[3])             \
                 : "r"(a[0]), "r"(a[1]), "r"(a[2]), "r"(a[3]),                \
                   "r"(b[0]), "r"(b[1]))

#define LDSM_X4(r0, r1, r2, r3, addr)                                         \
    asm volatile("ldmatrix.sync.aligned.m8n8.x4.shared.b16 {%0,%1,%2,%3}, [%4];" \
                 : "=r"(r0), "=r"(r1), "=r"(r2), "=r"(r3) : "r"(addr))

#define LDSM_X4_T(r0, r1, r2, r3, addr)                                       \
    asm volatile("ldmatrix.sync.aligned.m8n8.x4.trans.shared.b16 {%0,%1,%2,%3}, [%4];" \
                 : "=r"(r0), "=r"(r1), "=r"(r2), "=r"(r3) : "r"(addr))

__device__ __forceinline__ uint32_t pack_bf16x2(float a, float b) {
    __nv_bfloat162 p;
    p.x = __float2bfloat16(a);
    p.y = __float2bfloat16(b);
    return *(uint32_t*)&p;
}

// ---------------------------------------------------------------------------
// Pre-pass kernels
// ---------------------------------------------------------------------------
__global__ void bm_kernel(const int* __restrict__ rel_index,
                          const float* __restrict__ table,
                          const float* __restrict__ attn_mask) {
    int idx = blockIdx.x * blockDim.x + threadIdx.x;
    const int total = MASKW * HEADS * LEN * LEN;
    if (idx >= total) return;
    int qk = idx % (LEN * LEN);
    int h  = (idx / (LEN * LEN)) % HEADS;
    int w  = idx / (HEADS * LEN * LEN);
    g_bm[(w * HEADS + h) * BM_SLICE + qk] =
        table[rel_index[qk] * HEADS + h] + attn_mask[w * LEN * LEN + qk];
}

// Merged prep: x split (float4 range) + both weight transposes+splits
#define XN4 (NTOK * CH / 4)           // 2,408,448
#define WQN (THREEC * KDIM)           // 442,368
#define WPN (CH * KDIM)               // 147,456
__global__ void prep_kernel(const float* __restrict__ x,
                            const float* __restrict__ wq,
                            const float* __restrict__ wp) {
    int idx = blockIdx.x * blockDim.x + threadIdx.x;
    if (idx < XN4) {
        float4 v = ((const float4*)x)[idx];
        float a[4] = {v.x, v.y, v.z, v.w};
        __nv_bfloat162 h01, h23, l01, l23;
        __nv_bfloat16 hh[4];
        #pragma unroll
        for (int j = 0; j < 4; j++) hh[j] = __float2bfloat16(a[j]);
        h01.x = hh[0]; h01.y = hh[1]; h23.x = hh[2]; h23.y = hh[3];
        l01.x = __float2bfloat16(a[0] - __bfloat162float(hh[0]));
        l01.y = __float2bfloat16(a[1] - __bfloat162float(hh[1]));
        l23.x = __float2bfloat16(a[2] - __bfloat162float(hh[2]));
        l23.y = __float2bfloat16(a[3] - __bfloat162float(hh[3]));
        ((__nv_bfloat162*)g_x_hi)[2*idx]   = h01;
        ((__nv_bfloat162*)g_x_hi)[2*idx+1] = h23;
        ((__nv_bfloat162*)g_x_lo)[2*idx]   = l01;
        ((__nv_bfloat162*)g_x_lo)[2*idx+1] = l23;
    } else if (idx < XN4 + WQN) {
        int j = idx - XN4;
        int n = j / KDIM, k = j - n * KDIM;
        float v = wq[k * THREEC + n];
        __nv_bfloat16 h = __float2bfloat16(v);
        g_wq_hi[j] = h;
        g_wq_lo[j] = __float2bfloat16(v - __bfloat162float(h));
    } else if (idx < XN4 + WQN + WPN) {
        int j = idx - XN4 - WQN;
        int n = j / KDIM, k = j - n * KDIM;
        float v = wp[k * CH + n];
        __nv_bfloat16 h = __float2bfloat16(v);
        g_wp_hi[j] = h;
        g_wp_lo[j] = __float2bfloat16(v - __bfloat162float(h));
    }
}

// ---------------------------------------------------------------------------
// bf16x3 GEMM — proven R11 config: ldmatrix frags, 2-stage BK=32, 2 CTAs/SM.
// BM=BN=128, 256 threads (8 warps 2x4), warp tile 64x32, stride 40.
// ---------------------------------------------------------------------------
#define BSTRIDE 40
#define TILE_BF16 (128 * BSTRIDE)
#define STAGE_BF16 (4 * TILE_BF16)
#define GEMM_SMEM_BYTES (2 * STAGE_BF16 * 2)   // 81920

__device__ __forceinline__ void load_stage(
    const __nv_bfloat16* __restrict__ Ahi, const __nv_bfloat16* __restrict__ Alo,
    const __nv_bfloat16* __restrict__ Bhi, const __nv_bfloat16* __restrict__ Blo,
    __nv_bfloat16* st, int rowBase, int colBase, int k0, int tid)
{
    #pragma unroll
    for (int i = 0; i < 8; i++) {
        const int sel = i >> 1;
        int j   = tid + 256 * (i & 1);
        int row = j >> 2;
        int c8  = (j & 3) * 8;
        __nv_bfloat16* dst = st + sel * TILE_BF16 + row * BSTRIDE + c8;
        const __nv_bfloat16* src;
        if      (sel == 0) src = Ahi + (size_t)(rowBase + row) * KDIM + k0 + c8;
        else if (sel == 1) src = Alo + (size_t)(rowBase + row) * KDIM + k0 + c8;
        else if (sel == 2) src = Bhi + (size_t)(colBase + row) * KDIM + k0 + c8;
        else               src = Blo + (size_t)(colBase + row) * KDIM + k0 + c8;
        cp_async16(dst, src);
    }
}

__global__ void __launch_bounds__(256, 2) gemm_bf16x3_kernel(
    const __nv_bfloat16* __restrict__ Ahi, const __nv_bfloat16* __restrict__ Alo,
    const __nv_bfloat16* __restrict__ Bhi, const __nv_bfloat16* __restrict__ Blo,
    const float* __restrict__ bias, float* __restrict__ C,
    __nv_bfloat16* __restrict__ Chi, __nv_bfloat16* __restrict__ Clo, int Ntot)
{
    extern __shared__ __nv_bfloat16 smem[];

    const int tid  = threadIdx.x;
    const int lane = tid & 31;
    const int w    = tid >> 5;
    const int wm   = w >> 2;
    const int wn   = w & 3;
    const int g    = lane >> 3;
    const int li   = lane & 7;
    const int rowBase = blockIdx.y * 128;
    const int colBase = blockIdx.x * 128;
    const uint32_t sb = (uint32_t)__cvta_generic_to_shared(smem);

    float acc[4][4][4];
    #pragma unroll
    for (int i = 0; i < 4; i++)
        #pragma unroll
        for (int j = 0; j < 4; j++)
            #pragma unroll
            for (int r = 0; r < 4; r++) acc[i][j][r] = 0.f;

    const int nStages = KDIM / 32;  // 12

    load_stage(Ahi, Alo, Bhi, Blo, smem,              rowBase, colBase, 0,  tid);
    cp_async_commit();
    load_stage(Ahi, Alo, Bhi, Blo, smem + STAGE_BF16, rowBase, colBase, 32, tid);
    cp_async_commit();

    const int a_row_li = li + (g & 1) * 8;
    const int a_col_g  = (g >> 1) * 8;
    const int b_row_li = li + (g >> 1) * 8;
    const int b_col_g  = (g & 1) * 8;

    #pragma unroll 1
    for (int ks = 0; ks < nStages; ks++) {
        cp_async_wait1();
        __syncthreads();

        const uint32_t st = sb + ((ks & 1) * STAGE_BF16) * 2;
        const uint32_t ah_b = st;
        const uint32_t al_b = st + TILE_BF16 * 2;
        const uint32_t bh_b = st + 2 * TILE_BF16 * 2;
        const uint32_t bl_b = st + 3 * TILE_BF16 * 2;

        #pragma unroll
        for (int kk = 0; kk < 2; kk++) {
            const int acol = kk * 16 + a_col_g;
            const int bcol = kk * 16 + b_col_g;
            uint32_t ah[4][4], al[4][4], bh[2][4], bl[2][4];
            #pragma unroll
            for (int mt = 0; mt < 4; mt++) {
                int arow = wm * 64 + mt * 16 + a_row_li;
                uint32_t aoff = (uint32_t)(arow * BSTRIDE + acol) * 2;
                LDSM_X4(ah[mt][0], ah[mt][1], ah[mt][2], ah[mt][3], ah_b + aoff);
                LDSM_X4(al[mt][0], al[mt][1], al[mt][2], al[mt][3], al_b + aoff);
            }
            #pragma unroll
            for (int np = 0; np < 2; np++) {
                int brow = wn * 32 + np * 16 + b_row_li;
                uint32_t boff = (uint32_t)(brow * BSTRIDE + bcol) * 2;
                LDSM_X4(bh[np][0], bh[np][1], bh[np][2], bh[np][3], bh_b + boff);
                LDSM_X4(bl[np][0], bl[np][1], bl[np][2], bl[np][3], bl_b + boff);
            }
            #pragma unroll
            for (int mt = 0; mt < 4; mt++)
                #pragma unroll
                for (int np = 0; np < 2; np++) {
                    uint32_t bh0[2] = {bh[np][0], bh[np][1]};
                    uint32_t bh1[2] = {bh[np][2], bh[np][3]};
                    uint32_t bl0[2] = {bl[np][0], bl[np][1]};
                    uint32_t bl1[2] = {bl[np][2], bl[np][3]};
                    MMA_BF16(acc[mt][np * 2],     ah[mt], bh0);
                    MMA_BF16(acc[mt][np * 2],     ah[mt], bl0);
                    MMA_BF16(acc[mt][np * 2],     al[mt], bh0);
                    MMA_BF16(acc[mt][np * 2 + 1], ah[mt], bh1);
                    MMA_BF16(acc[mt][np * 2 + 1], ah[mt], bl1);
                    MMA_BF16(acc[mt][np * 2 + 1], al[mt], bh1);
                }
        }
        __syncthreads();
        if (ks + 2 < nStages) {
            load_stage(Ahi, Alo, Bhi, Blo, smem + (ks & 1) * STAGE_BF16,
                       rowBase, colBase, (ks + 2) * 32, tid);
        }
        cp_async_commit();
    }

    // Epilogue
    #pragma unroll
    for (int mt = 0; mt < 4; mt++) {
        int row = rowBase + wm * 64 + mt * 16 + (lane >> 2);
        #pragma unroll
        for (int nt = 0; nt < 4; nt++) {
            int col = colBase + wn * 32 + nt * 8 + (lane & 3) * 2;
            float b0 = bias[col], b1 = bias[col + 1];
            float v00 = acc[mt][nt][0] + b0, v01 = acc[mt][nt][1] + b1;
            float v10 = acc[mt][nt][2] + b0, v11 = acc[mt][nt][3] + b1;
            if (Chi) {
                __nv_bfloat162 h0, h1, l0, l1;
                h0.x = __float2bfloat16(v00); h0.y = __float2bfloat16(v01);
                h1.x = __float2bfloat16(v10); h1.y = __float2bfloat16(v11);
                l0.x = __float2bfloat16(v00 - __bfloat162float(h0.x));
                l0.y = __float2bfloat16(v01 - __bfloat162float(h0.y));
                l1.x = __float2bfloat16(v10 - __bfloat162float(h1.x));
                l1.y = __float2bfloat16(v11 - __bfloat162float(h1.y));
                *(__nv_bfloat162*)&Chi[(size_t)row * Ntot + col]       = h0;
                *(__nv_bfloat162*)&Chi[(size_t)(row + 8) * Ntot + col] = h1;
                *(__nv_bfloat162*)&Clo[(size_t)row * Ntot + col]       = l0;
                *(__nv_bfloat162*)&Clo[(size_t)(row + 8) * Ntot + col] = l1;
            } else {
                *(float2*)&C[(size_t)row * Ntot + col]       = make_float2(v00, v01);
                *(float2*)&C[(size_t)(row + 8) * Ntot + col] = make_float2(v10, v11);
            }
        }
    }
}

// ---------------------------------------------------------------------------
// Tensor-core window attention — proven R11 config: single window per block,
// 128 threads, FA2 register-P, cp.async pre-split QKV + staged bias/mask.
// Smem: 6 regions x 2560 bf16 (stride 40) + bm floats. 40448 B -> 5 CTAs/SM.
// ---------------------------------------------------------------------------
#define AQS 40
#define A_BM 15360
#define ATTN_SMEM_BYTES (30720 + BM_SLICE * 4)

__global__ void __launch_bounds__(128) attn_mma_kernel() {
    extern __shared__ __nv_bfloat16 asm_s[];
    float* bm_s = (float*)(asm_s + A_BM);
    const int tid  = threadIdx.x;
    const int lane = tid & 31;
    const int w    = tid >> 5;
    const int h = blockIdx.x;
    const int b = blockIdx.y;
    const float scale = 0.17677669529663687f;   // 1/sqrt(32)

    for (int i = tid; i < 6 * 15 * 20; i += 128) {
        int sel = i / 300;
        int rem = i - sel * 300;
        int r = 49 + rem / 20;
        int c2 = (rem % 20) * 2;
        *(uint32_t*)(asm_s + sel * 2560 + r * AQS + c2) = 0u;
    }
    {
        const __nv_bfloat16* hi = g_qkv_hi + (size_t)b * LEN * THREEC + h * HDIM;
        const __nv_bfloat16* lo = g_qkv_lo + (size_t)b * LEN * THREEC + h * HDIM;
        for (int i = tid; i < 6 * 49 * 4; i += 128) {
            int sel = i / 196;
            int rem = i - sel * 196;
            int r = rem >> 2, c8 = (rem & 3) * 8;
            const __nv_bfloat16* base = (sel & 1) ? lo : hi;
            cp_async16(asm_s + sel * 2560 + r * AQS + c8,
                       base + (size_t)r * THREEC + (sel >> 1) * CH + c8);
        }
    }
    cp_async_commit();
    {
        const float* bm_g = g_bm + (size_t)((b & 63) * HEADS + h) * BM_SLICE;
        for (int i = tid; i < BM_SLICE / 4; i += 128)
            cp_async16(bm_s + i * 4, bm_g + i * 4);
    }
    cp_async_commit();
    cp_async_wait1();
    __syncthreads();

    const uint32_t sb = (uint32_t)__cvta_generic_to_shared(asm_s);
    const int g = lane >> 3;
    const int li = lane & 7;

    float acc[8][4];
    #pragma unroll
    for (int nt = 0; nt < 8; nt++)
        #pragma unroll
        for (int r = 0; r < 4; r++) acc[nt][r] = 0.f;

    #pragma unroll
    for (int ks = 0; ks < 2; ks++) {
        int arow = 16 * w + li + (g & 1) * 8;
        int acol = ks * 16 + (g >> 1) * 8;
        uint32_t aaddr_off = (uint32_t)(arow * AQS + acol) * 2;
        uint32_t qh_[4], ql_[4];
        LDSM_X4(qh_[0], qh_[1], qh_[2], qh_[3], sb + 0 * 2560 * 2 + aaddr_off);
        LDSM_X4(ql_[0], ql_[1], ql_[2], ql_[3], sb + 1 * 2560 * 2 + aaddr_off);

        #pragma unroll
        for (int np = 0; np < 4; np++) {
            int brow = np * 16 + li + (g >> 1) * 8;
            int bcol = ks * 16 + (g & 1) * 8;
            uint32_t baddr_off = (uint32_t)(brow * AQS + bcol) * 2;
            uint32_t kh_[4], kl_[4];
            LDSM_X4(kh_[0], kh_[1], kh_[2], kh_[3], sb + 2 * 2560 * 2 + baddr_off);
            LDSM_X4(kl_[0], kl_[1], kl_[2], kl_[3], sb + 3 * 2560 * 2 + baddr_off);
            uint32_t bh0[2] = {kh_[0], kh_[1]}, bh1[2] = {kh_[2], kh_[3]};
            uint32_t bl0[2] = {kl_[0], kl_[1]}, bl1[2] = {kl_[2], kl_[3]};
            MMA_BF16(acc[np * 2],     qh_, bh0);
            MMA_BF16(acc[np * 2],     qh_, bl0);
            MMA_BF16(acc[np * 2],     ql_, bh0);
            MMA_BF16(acc[np * 2 + 1], qh_, bh1);
            MMA_BF16(acc[np * 2 + 1], qh_, bl1);
            MMA_BF16(acc[np * 2 + 1], ql_, bh1);
        }
    }

    cp_async_wait0();
    __syncthreads();

    const int qi0 = 16 * w + (lane >> 2);
    const int qi1 = qi0 + 8;
    #pragma unroll
    for (int nt = 0; nt < 8; nt++) {
        int kj = nt * 8 + (lane & 3) * 2;
        #pragma unroll
        for (int e = 0; e < 2; e++) {
            int col = kj + e;
            float bm0 = 0.f, bm1 = 0.f;
            if (col < LEN) {
                if (qi0 < LEN) bm0 = bm_s[qi0 * LEN + col];
                if (qi1 < LEN) bm1 = bm_s[qi1 * LEN + col];
            } else { bm0 = -1e30f; bm1 = -1e30f; }
            acc[nt][e]     = fmaf(acc[nt][e],     scale, bm0);
            acc[nt][e + 2] = fmaf(acc[nt][e + 2], scale, bm1);
        }
    }

    float m0 = -1e30f, m1 = -1e30f;
    #pragma unroll
    for (int nt = 0; nt < 8; nt++) {
        m0 = fmaxf(m0, fmaxf(acc[nt][0], acc[nt][1]));
        m1 = fmaxf(m1, fmaxf(acc[nt][2], acc[nt][3]));
    }
    m0 = fmaxf(m0, __shfl_xor_sync(0xffffffffu, m0, 1));
    m0 = fmaxf(m0, __shfl_xor_sync(0xffffffffu, m0, 2));
    m1 = fmaxf(m1, __shfl_xor_sync(0xffffffffu, m1, 1));
    m1 = fmaxf(m1, __shfl_xor_sync(0xffffffffu, m1, 2));
    float s0 = 0.f, s1 = 0.f;
    #pragma unroll
    for (int nt = 0; nt < 8; nt++) {
        acc[nt][0] = __expf(acc[nt][0] - m0);
        acc[nt][1] = __expf(acc[nt][1] - m0);
        acc[nt][2] = __expf(acc[nt][2] - m1);
        acc[nt][3] = __expf(acc[nt][3] - m1);
        s0 += acc[nt][0] + acc[nt][1];
        s1 += acc[nt][2] + acc[nt][3];
    }
    s0 += __shfl_xor_sync(0xffffffffu, s0, 1);
    s0 += __shfl_xor_sync(0xffffffffu, s0, 2);
    s1 += __shfl_xor_sync(0xffffffffu, s1, 1);
    s1 += __shfl_xor_sync(0xffffffffu, s1, 2);
    float i0 = 1.f / s0, i1 = 1.f / s1;

    float oacc[4][4];
    #pragma unroll
    for (int nt = 0; nt < 4; nt++)
        #pragma unroll
        for (int r = 0; r < 4; r++) oacc[nt][r] = 0.f;

    #pragma unroll
    for (int ks = 0; ks < 4; ks++) {
        float p00 = acc[2*ks][0]   * i0, p01 = acc[2*ks][1]   * i0;
        float p02 = acc[2*ks][2]   * i1, p03 = acc[2*ks][3]   * i1;
        float p10 = acc[2*ks+1][0] * i0, p11 = acc[2*ks+1][1] * i0;
        float p12 = acc[2*ks+1][2] * i1, p13 = acc[2*ks+1][3] * i1;

        uint32_t ph_[4], pl_[4];
        ph_[0] = pack_bf16x2(p00, p01);
        ph_[1] = pack_bf16x2(p02, p03);
        ph_[2] = pack_bf16x2(p10, p11);
        ph_[3] = pack_bf16x2(p12, p13);
        {
            __nv_bfloat162 hh;
            *(uint32_t*)&hh = ph_[0];
            pl_[0] = pack_bf16x2(p00 - __bfloat162float(hh.x), p01 - __bfloat162float(hh.y));
            *(uint32_t*)&hh = ph_[1];
            pl_[1] = pack_bf16x2(p02 - __bfloat162float(hh.x), p03 - __bfloat162float(hh.y));
            *(uint32_t*)&hh = ph_[2];
            pl_[2] = pack_bf16x2(p10 - __bfloat162float(hh.x), p11 - __bfloat162float(hh.y));
            *(uint32_t*)&hh = ph_[3];
            pl_[3] = pack_bf16x2(p12 - __bfloat162float(hh.x), p13 - __bfloat162float(hh.y));
        }

        #pragma unroll
        for (int dp = 0; dp < 2; dp++) {
            int vrow = ks * 16 + li + (g & 1) * 8;
            int vcol = dp * 16 + (g >> 1) * 8;
            uint32_t voff = (uint32_t)(vrow * AQS + vcol) * 2;
            uint32_t vh_[4], vl_[4];
            LDSM_X4_T(vh_[0], vh_[1], vh_[2], vh_[3], sb + 4 * 2560 * 2 + voff);
            LDSM_X4_T(vl_[0], vl_[1], vl_[2], vl_[3], sb + 5 * 2560 * 2 + voff);
            uint32_t bh0[2] = {vh_[0], vh_[1]}, bh1[2] = {vh_[2], vh_[3]};
            uint32_t bl0[2] = {vl_[0], vl_[1]}, bl1[2] = {vl_[2], vl_[3]};
            MMA_BF16(oacc[dp * 2],     ph_, bh0);
            MMA_BF16(oacc[dp * 2],     ph_, bl0);
            MMA_BF16(oacc[dp * 2],     pl_, bh0);
            MMA_BF16(oacc[dp * 2 + 1], ph_, bh1);
            MMA_BF16(oacc[dp * 2 + 1], ph_, bl1);
            MMA_BF16(oacc[dp * 2 + 1], pl_, bh1);
        }
    }

    #pragma unroll
    for (int nt = 0; nt < 4; nt++) {
        int d = nt * 8 + (lane & 3) * 2;
        #pragma unroll
        for (int rr = 0; rr < 2; rr++) {
            int qi = (rr == 0) ? qi0 : qi1;
            if (qi < LEN) {
                float v0 = oacc[nt][rr * 2], v1 = oacc[nt][rr * 2 + 1];
                __nv_bfloat162 hh, ll;
                hh.x = __float2bfloat16(v0); hh.y = __float2bfloat16(v1);
                ll.x = __float2bfloat16(v0 - __bfloat162float(hh.x));
                ll.y = __float2bfloat16(v1 - __bfloat162float(hh.y));
                size_t off = ((size_t)b * LEN + qi) * CH + h * HDIM + d;
                *(__nv_bfloat162*)(g_ao_hi + off) = hh;
                *(__nv_bfloat162*)(g_ao_lo + off) = ll;
            }
        }
    }
}

// ---------------------------------------------------------------------------
// Launch
// ---------------------------------------------------------------------------
extern "C" void kernel_launch(void* const* d_in, const int* in_sizes, int n_in,
                              void* d_out, int out_size) {
    const float* x          = (const float*)d_in[0];
    const int*   rel_index  = (const int*)d_in[1];
    const float* attn_mask  = (const float*)d_in[2];
    const float* qkv_w      = (const float*)d_in[3];
    const float* qkv_b      = (const float*)d_in[4];
    const float* bias_table = (const float*)d_in[5];
    const float* proj_w     = (const float*)d_in[6];
    const float* proj_b     = (const float*)d_in[7];
    float* out = (float*)d_out;

    __nv_bfloat16 *qkvh, *qkvl, *xh, *xl, *aoh, *aol, *wqh, *wql, *wph, *wpl;
    cudaGetSymbolAddress((void**)&qkvh, g_qkv_hi);
    cudaGetSymbolAddress((void**)&qkvl, g_qkv_lo);
    cudaGetSymbolAddress((void**)&xh,  g_x_hi);
    cudaGetSymbolAddress((void**)&xl,  g_x_lo);
    cudaGetSymbolAddress((void**)&aoh, g_ao_hi);
    cudaGetSymbolAddress((void**)&aol, g_ao_lo);
    cudaGetSymbolAddress((void**)&wqh, g_wq_hi);
    cudaGetSymbolAddress((void**)&wql, g_wq_lo);
    cudaGetSymbolAddress((void**)&wph, g_wp_hi);
    cudaGetSymbolAddress((void**)&wpl, g_wp_lo);

    cudaFuncSetAttribute(gemm_bf16x3_kernel,
                         cudaFuncAttributeMaxDynamicSharedMemorySize,
                         GEMM_SMEM_BYTES);
    cudaFuncSetAttribute(attn_mma_kernel,
                         cudaFuncAttributeMaxDynamicSharedMemorySize,
                         ATTN_SMEM_BYTES);

    // 1) combined bias+mask table
    {
        int total = MASKW * HEADS * LEN * LEN;
        bm_kernel<<<(total + 255) / 256, 256>>>(rel_index, bias_table, attn_mask);
    }
    // 2) merged prep: x split + both weight transposes/splits
    {
        int total = XN4 + WQN + WPN;
        prep_kernel<<<(total + 255) / 256, 256>>>(x, qkv_w, proj_w);
    }
    // 3) qkv GEMM -> split bf16 output
    {
        dim3 grid(THREEC / 128, NTOK / 128);
        gemm_bf16x3_kernel<<<grid, 256, GEMM_SMEM_BYTES>>>(
            xh, xl, wqh, wql, qkv_b, nullptr, qkvh, qkvl, THREEC);
    }
    // 4) attention (single window per block, register-P)
    {
        dim3 grid(HEADS, BATCH);
        attn_mma_kernel<<<grid, 128, ATTN_SMEM_BYTES>>>();
    }
    // 5) proj GEMM -> fp32 out
    {
        dim3 grid(CH / 128, NTOK / 128);
        gemm_bf16x3_kernel<<<grid, 256, GEMM_SMEM_BYTES>>>(
            aoh, aol, wph, wpl, proj_b, out, nullptr, nullptr, CH);
    }
}

// round 17
// speedup vs baseline: 1.5612x; 1.0418x over previous
#include <cuda_runtime.h>
#include <cuda_bf16.h>
#include <math.h>
#include <stdint.h>

// Problem constants
#define BATCH   2048
#define LEN     49
#define CH      384
#define HEADS   12
#define HDIM    32
#define THREEC  1152
#define NTOK    (BATCH*LEN)   // 100352
#define KDIM    384
#define MASKW   64
#define BM_SLICE 2432         // padded 49*49 -> 16B-aligned slices (tail stays 0)

// Scratch (device globals — no allocations allowed)
__device__ __nv_bfloat16 g_qkv_hi[NTOK * THREEC], g_qkv_lo[NTOK * THREEC];
__device__ float g_bm[MASKW * HEADS * BM_SLICE + 16];
__device__ __nv_bfloat16 g_x_hi[NTOK * CH],  g_x_lo[NTOK * CH];
__device__ __nv_bfloat16 g_ao_hi[NTOK * CH], g_ao_lo[NTOK * CH];
__device__ __nv_bfloat16 g_wq_hi[THREEC * KDIM], g_wq_lo[THREEC * KDIM]; // [N][K]
__device__ __nv_bfloat16 g_wp_hi[CH * KDIM],     g_wp_lo[CH * KDIM];     // [N][K]

// ---------------------------------------------------------------------------
// Helpers
// ---------------------------------------------------------------------------
__device__ __forceinline__ void cp_async16(void* smem_ptr, const void* gmem_ptr) {
    uint32_t s = (uint32_t)__cvta_generic_to_shared(smem_ptr);
    asm volatile("cp.async.cg.shared.global [%0], [%1], 16;\n"
                 :: "r"(s), "l"(gmem_ptr) : "memory");
}
__device__ __forceinline__ void cp_async_commit() {
    asm volatile("cp.async.commit_group;\n" ::: "memory");
}
__device__ __forceinline__ void cp_async_wait1() {
    asm volatile("cp.async.wait_group 1;\n" ::: "memory");
}
__device__ __forceinline__ void cp_async_wait0() {
    asm volatile("cp.async.wait_group 0;\n" ::: "memory");
}

#define MMA_BF16(d, a, b)                                                     \
    asm volatile("mma.sync.aligned.m16n8k16.row.col.f32.bf16.bf16.f32 "       \
                 "{%0,%1,%2,%3}, {%4,%5,%6,%7}, {%8,%9}, {%0,%1,%2,%3};\n"    \
                 : "+f"(d[0]), "+f"(d[1]), "+f"(d[2]), "+f"(d[3])             \
                 : "r"(a[0]), "r"(a[1]), "r"(a[2]), "r"(a[3]),                \
                   "r"(b[0]), "r"(b[1]))

#define LDSM_X4(r0, r1, r2, r3, addr)                                         \
    asm volatile("ldmatrix.sync.aligned.m8n8.x4.shared.b16 {%0,%1,%2,%3}, [%4];" \
                 : "=r"(r0), "=r"(r1), "=r"(r2), "=r"(r3) : "r"(addr))

#define LDSM_X4_T(r0, r1, r2, r3, addr)                                       \
    asm volatile("ldmatrix.sync.aligned.m8n8.x4.trans.shared.b16 {%0,%1,%2,%3}, [%4];" \
                 : "=r"(r0), "=r"(r1), "=r"(r2), "=r"(r3) : "r"(addr))

__device__ __forceinline__ uint32_t pack_bf16x2(float a, float b) {
    __nv_bfloat162 p;
    p.x = __float2bfloat16(a);
    p.y = __float2bfloat16(b);
    return *(uint32_t*)&p;
}

// ---------------------------------------------------------------------------
// Pre-pass kernels
// ---------------------------------------------------------------------------
__global__ void bm_kernel(const int* __restrict__ rel_index,
                          const float* __restrict__ table,
                          const float* __restrict__ attn_mask) {
    int idx = blockIdx.x * blockDim.x + threadIdx.x;
    const int total = MASKW * HEADS * LEN * LEN;
    if (idx >= total) return;
    int qk = idx % (LEN * LEN);
    int h  = (idx / (LEN * LEN)) % HEADS;
    int w  = idx / (HEADS * LEN * LEN);
    g_bm[(w * HEADS + h) * BM_SLICE + qk] =
        table[rel_index[qk] * HEADS + h] + attn_mask[w * LEN * LEN + qk];
}

// Merged prep: x split (float4 range) + both weight transposes+splits
#define XN4 (NTOK * CH / 4)           // 2,408,448
#define WQN (THREEC * KDIM)           // 442,368
#define WPN (CH * KDIM)               // 147,456
__global__ void prep_kernel(const float* __restrict__ x,
                            const float* __restrict__ wq,
                            const float* __restrict__ wp) {
    int idx = blockIdx.x * blockDim.x + threadIdx.x;
    if (idx < XN4) {
        float4 v = ((const float4*)x)[idx];
        float a[4] = {v.x, v.y, v.z, v.w};
        __nv_bfloat162 h01, h23, l01, l23;
        __nv_bfloat16 hh[4];
        #pragma unroll
        for (int j = 0; j < 4; j++) hh[j] = __float2bfloat16(a[j]);
        h01.x = hh[0]; h01.y = hh[1]; h23.x = hh[2]; h23.y = hh[3];
        l01.x = __float2bfloat16(a[0] - __bfloat162float(hh[0]));
        l01.y = __float2bfloat16(a[1] - __bfloat162float(hh[1]));
        l23.x = __float2bfloat16(a[2] - __bfloat162float(hh[2]));
        l23.y = __float2bfloat16(a[3] - __bfloat162float(hh[3]));
        ((__nv_bfloat162*)g_x_hi)[2*idx]   = h01;
        ((__nv_bfloat162*)g_x_hi)[2*idx+1] = h23;
        ((__nv_bfloat162*)g_x_lo)[2*idx]   = l01;
        ((__nv_bfloat162*)g_x_lo)[2*idx+1] = l23;
    } else if (idx < XN4 + WQN) {
        int j = idx - XN4;
        int n = j / KDIM, k = j - n * KDIM;
        float v = wq[k * THREEC + n];
        __nv_bfloat16 h = __float2bfloat16(v);
        g_wq_hi[j] = h;
        g_wq_lo[j] = __float2bfloat16(v - __bfloat162float(h));
    } else if (idx < XN4 + WQN + WPN) {
        int j = idx - XN4 - WQN;
        int n = j / KDIM, k = j - n * KDIM;
        float v = wp[k * CH + n];
        __nv_bfloat16 h = __float2bfloat16(v);
        g_wp_hi[j] = h;
        g_wp_lo[j] = __float2bfloat16(v - __bfloat162float(h));
    }
}

// ---------------------------------------------------------------------------
// bf16x3 GEMM — proven R11 config (UNCHANGED): ldmatrix frags, 2-stage BK=32,
// 2 CTAs/SM, BM=BN=128, 256 threads, warp tile 64x32, stride 40.
// ---------------------------------------------------------------------------
#define BSTRIDE 40
#define TILE_BF16 (128 * BSTRIDE)
#define STAGE_BF16 (4 * TILE_BF16)
#define GEMM_SMEM_BYTES (2 * STAGE_BF16 * 2)   // 81920

__device__ __forceinline__ void load_stage(
    const __nv_bfloat16* __restrict__ Ahi, const __nv_bfloat16* __restrict__ Alo,
    const __nv_bfloat16* __restrict__ Bhi, const __nv_bfloat16* __restrict__ Blo,
    __nv_bfloat16* st, int rowBase, int colBase, int k0, int tid)
{
    #pragma unroll
    for (int i = 0; i < 8; i++) {
        const int sel = i >> 1;
        int j   = tid + 256 * (i & 1);
        int row = j >> 2;
        int c8  = (j & 3) * 8;
        __nv_bfloat16* dst = st + sel * TILE_BF16 + row * BSTRIDE + c8;
        const __nv_bfloat16* src;
        if      (sel == 0) src = Ahi + (size_t)(rowBase + row) * KDIM + k0 + c8;
        else if (sel == 1) src = Alo + (size_t)(rowBase + row) * KDIM + k0 + c8;
        else if (sel == 2) src = Bhi + (size_t)(colBase + row) * KDIM + k0 + c8;
        else               src = Blo + (size_t)(colBase + row) * KDIM + k0 + c8;
        cp_async16(dst, src);
    }
}

__global__ void __launch_bounds__(256, 2) gemm_bf16x3_kernel(
    const __nv_bfloat16* __restrict__ Ahi, const __nv_bfloat16* __restrict__ Alo,
    const __nv_bfloat16* __restrict__ Bhi, const __nv_bfloat16* __restrict__ Blo,
    const float* __restrict__ bias, float* __restrict__ C,
    __nv_bfloat16* __restrict__ Chi, __nv_bfloat16* __restrict__ Clo, int Ntot)
{
    extern __shared__ __nv_bfloat16 smem[];

    const int tid  = threadIdx.x;
    const int lane = tid & 31;
    const int w    = tid >> 5;
    const int wm   = w >> 2;
    const int wn   = w & 3;
    const int g    = lane >> 3;
    const int li   = lane & 7;
    const int rowBase = blockIdx.y * 128;
    const int colBase = blockIdx.x * 128;
    const uint32_t sb = (uint32_t)__cvta_generic_to_shared(smem);

    float acc[4][4][4];
    #pragma unroll
    for (int i = 0; i < 4; i++)
        #pragma unroll
        for (int j = 0; j < 4; j++)
            #pragma unroll
            for (int r = 0; r < 4; r++) acc[i][j][r] = 0.f;

    const int nStages = KDIM / 32;  // 12

    load_stage(Ahi, Alo, Bhi, Blo, smem,              rowBase, colBase, 0,  tid);
    cp_async_commit();
    load_stage(Ahi, Alo, Bhi, Blo, smem + STAGE_BF16, rowBase, colBase, 32, tid);
    cp_async_commit();

    const int a_row_li = li + (g & 1) * 8;
    const int a_col_g  = (g >> 1) * 8;
    const int b_row_li = li + (g >> 1) * 8;
    const int b_col_g  = (g & 1) * 8;

    #pragma unroll 1
    for (int ks = 0; ks < nStages; ks++) {
        cp_async_wait1();
        __syncthreads();

        const uint32_t st = sb + ((ks & 1) * STAGE_BF16) * 2;
        const uint32_t ah_b = st;
        const uint32_t al_b = st + TILE_BF16 * 2;
        const uint32_t bh_b = st + 2 * TILE_BF16 * 2;
        const uint32_t bl_b = st + 3 * TILE_BF16 * 2;

        #pragma unroll
        for (int kk = 0; kk < 2; kk++) {
            const int acol = kk * 16 + a_col_g;
            const int bcol = kk * 16 + b_col_g;
            uint32_t ah[4][4], al[4][4], bh[2][4], bl[2][4];
            #pragma unroll
            for (int mt = 0; mt < 4; mt++) {
                int arow = wm * 64 + mt * 16 + a_row_li;
                uint32_t aoff = (uint32_t)(arow * BSTRIDE + acol) * 2;
                LDSM_X4(ah[mt][0], ah[mt][1], ah[mt][2], ah[mt][3], ah_b + aoff);
                LDSM_X4(al[mt][0], al[mt][1], al[mt][2], al[mt][3], al_b + aoff);
            }
            #pragma unroll
            for (int np = 0; np < 2; np++) {
                int brow = wn * 32 + np * 16 + b_row_li;
                uint32_t boff = (uint32_t)(brow * BSTRIDE + bcol) * 2;
                LDSM_X4(bh[np][0], bh[np][1], bh[np][2], bh[np][3], bh_b + boff);
                LDSM_X4(bl[np][0], bl[np][1], bl[np][2], bl[np][3], bl_b + boff);
            }
            #pragma unroll
            for (int mt = 0; mt < 4; mt++)
                #pragma unroll
                for (int np = 0; np < 2; np++) {
                    uint32_t bh0[2] = {bh[np][0], bh[np][1]};
                    uint32_t bh1[2] = {bh[np][2], bh[np][3]};
                    uint32_t bl0[2] = {bl[np][0], bl[np][1]};
                    uint32_t bl1[2] = {bl[np][2], bl[np][3]};
                    MMA_BF16(acc[mt][np * 2],     ah[mt], bh0);
                    MMA_BF16(acc[mt][np * 2],     ah[mt], bl0);
                    MMA_BF16(acc[mt][np * 2],     al[mt], bh0);
                    MMA_BF16(acc[mt][np * 2 + 1], ah[mt], bh1);
                    MMA_BF16(acc[mt][np * 2 + 1], ah[mt], bl1);
                    MMA_BF16(acc[mt][np * 2 + 1], al[mt], bh1);
                }
        }
        __syncthreads();
        if (ks + 2 < nStages) {
            load_stage(Ahi, Alo, Bhi, Blo, smem + (ks & 1) * STAGE_BF16,
                       rowBase, colBase, (ks + 2) * 32, tid);
        }
        cp_async_commit();
    }

    // Epilogue
    #pragma unroll
    for (int mt = 0; mt < 4; mt++) {
        int row = rowBase + wm * 64 + mt * 16 + (lane >> 2);
        #pragma unroll
        for (int nt = 0; nt < 4; nt++) {
            int col = colBase + wn * 32 + nt * 8 + (lane & 3) * 2;
            float b0 = bias[col], b1 = bias[col + 1];
            float v00 = acc[mt][nt][0] + b0, v01 = acc[mt][nt][1] + b1;
            float v10 = acc[mt][nt][2] + b0, v11 = acc[mt][nt][3] + b1;
            if (Chi) {
                __nv_bfloat162 h0, h1, l0, l1;
                h0.x = __float2bfloat16(v00); h0.y = __float2bfloat16(v01);
                h1.x = __float2bfloat16(v10); h1.y = __float2bfloat16(v11);
                l0.x = __float2bfloat16(v00 - __bfloat162float(h0.x));
                l0.y = __float2bfloat16(v01 - __bfloat162float(h0.y));
                l1.x = __float2bfloat16(v10 - __bfloat162float(h1.x));
                l1.y = __float2bfloat16(v11 - __bfloat162float(h1.y));
                *(__nv_bfloat162*)&Chi[(size_t)row * Ntot + col]       = h0;
                *(__nv_bfloat162*)&Chi[(size_t)(row + 8) * Ntot + col] = h1;
                *(__nv_bfloat162*)&Clo[(size_t)row * Ntot + col]       = l0;
                *(__nv_bfloat162*)&Clo[(size_t)(row + 8) * Ntot + col] = l1;
            } else {
                *(float2*)&C[(size_t)row * Ntot + col]       = make_float2(v00, v01);
                *(float2*)&C[(size_t)(row + 8) * Ntot + col] = make_float2(v10, v11);
            }
        }
    }
}

// ---------------------------------------------------------------------------
// Tensor-core window attention (bf16x3, FA2 register-P) — ALU-trimmed:
// unrolled sel loops (no int division), one-divide pad zeroing, branch-free
// bias/mask apply (clamped rows + zero-padded bm slices).
// Smem: 6 regions x 2560 bf16 (stride 40) + bm floats. 40448 B -> 5 CTAs/SM.
// ---------------------------------------------------------------------------
#define AQS 40
#define A_BM 15360
#define ATTN_SMEM_BYTES (30720 + BM_SLICE * 4)

__global__ void __launch_bounds__(128) attn_mma_kernel() {
    extern __shared__ __nv_bfloat16 asm_s[];
    float* bm_s = (float*)(asm_s + A_BM);
    const int tid  = threadIdx.x;
    const int lane = tid & 31;
    const int w    = tid >> 5;
    const int h = blockIdx.x;
    const int b = blockIdx.y;
    const float scale = 0.17677669529663687f;   // 1/sqrt(32)

    // Zero pad rows 49..63 (cols 0..39): 75 uint4 chunks per region, one divide.
    {
        const int zr = tid / 5;          // 0..25 (use <15)
        const int zc = tid - zr * 5;     // 0..4
        if (tid < 75) {
            uint4 z = make_uint4(0u, 0u, 0u, 0u);
            __nv_bfloat16* rowp = asm_s + (49 + zr) * AQS + zc * 8;
            #pragma unroll
            for (int sel = 0; sel < 6; sel++)
                *(uint4*)(rowp + sel * 2560) = z;
        }
    }
    // cp.async pre-split Q,K,V (rows 0..48), sel unrolled — group 1
    {
        const __nv_bfloat16* hi = g_qkv_hi + (size_t)b * LEN * THREEC + h * HDIM;
        const __nv_bfloat16* lo = g_qkv_lo + (size_t)b * LEN * THREEC + h * HDIM;
        #pragma unroll
        for (int sel = 0; sel < 6; sel++) {
            const __nv_bfloat16* base = ((sel & 1) ? lo : hi) + (sel >> 1) * CH;
            __nv_bfloat16* dsts = asm_s + sel * 2560;
            #pragma unroll
            for (int t = 0; t < 2; t++) {
                int i = tid + t * 128;
                if (i < 196) {
                    int r = i >> 2, c8 = (i & 3) * 8;
                    cp_async16(dsts + r * AQS + c8, base + (size_t)r * THREEC + c8);
                }
            }
        }
    }
    cp_async_commit();
    // cp.async bias+mask slice — group 2
    {
        const float* bm_g = g_bm + (size_t)((b & 63) * HEADS + h) * BM_SLICE;
        #pragma unroll
        for (int t = 0; t < 5; t++) {
            int i = tid + t * 128;
            if (i < BM_SLICE / 4)
                cp_async16(bm_s + i * 4, bm_g + i * 4);
        }
    }
    cp_async_commit();
    cp_async_wait1();
    __syncthreads();

    const uint32_t sb = (uint32_t)__cvta_generic_to_shared(asm_s);
    const int g = lane >> 3;
    const int li = lane & 7;

    // --- S = Q K^T (bf16x3) ---
    float acc[8][4];
    #pragma unroll
    for (int nt = 0; nt < 8; nt++)
        #pragma unroll
        for (int r = 0; r < 4; r++) acc[nt][r] = 0.f;

    #pragma unroll
    for (int ks = 0; ks < 2; ks++) {
        int arow = 16 * w + li + (g & 1) * 8;
        int acol = ks * 16 + (g >> 1) * 8;
        uint32_t aaddr_off = (uint32_t)(arow * AQS + acol) * 2;
        uint32_t qh_[4], ql_[4];
        LDSM_X4(qh_[0], qh_[1], qh_[2], qh_[3], sb + 0 * 2560 * 2 + aaddr_off);
        LDSM_X4(ql_[0], ql_[1], ql_[2], ql_[3], sb + 1 * 2560 * 2 + aaddr_off);

        #pragma unroll
        for (int np = 0; np < 4; np++) {
            int brow = np * 16 + li + (g >> 1) * 8;
            int bcol = ks * 16 + (g & 1) * 8;
            uint32_t baddr_off = (uint32_t)(brow * AQS + bcol) * 2;
            uint32_t kh_[4], kl_[4];
            LDSM_X4(kh_[0], kh_[1], kh_[2], kh_[3], sb + 2 * 2560 * 2 + baddr_off);
            LDSM_X4(kl_[0], kl_[1], kl_[2], kl_[3], sb + 3 * 2560 * 2 + baddr_off);
            uint32_t bh0[2] = {kh_[0], kh_[1]}, bh1[2] = {kh_[2], kh_[3]};
            uint32_t bl0[2] = {kl_[0], kl_[1]}, bl1[2] = {kl_[2], kl_[3]};
            MMA_BF16(acc[np * 2],     qh_, bh0);
            MMA_BF16(acc[np * 2],     qh_, bl0);
            MMA_BF16(acc[np * 2],     ql_, bh0);
            MMA_BF16(acc[np * 2 + 1], qh_, bh1);
            MMA_BF16(acc[np * 2 + 1], qh_, bl1);
            MMA_BF16(acc[np * 2 + 1], ql_, bh1);
        }
    }

    cp_async_wait0();
    __syncthreads();

    // --- scale + bias+mask: branch-free ---
    // Rows >= LEN are discarded later; clamp their bm row to 0 (finite values).
    // Cols >= LEN read the zero-initialized slice padding (in-bounds) and are
    // overridden to -1e30 via selp; nt<6 has col<=47 so no override needed.
    const int qi0 = 16 * w + (lane >> 2);
    const int qi1 = qi0 + 8;
    const int r0 = (qi0 < LEN) ? qi0 * LEN : 0;
    const int r1 = (qi1 < LEN) ? qi1 * LEN : 0;
    const int cbase = (lane & 3) * 2;
    #pragma unroll
    for (int nt = 0; nt < 8; nt++) {
        #pragma unroll
        for (int e = 0; e < 2; e++) {
            int col = nt * 8 + cbase + e;
            float v0 = bm_s[r0 + col];
            float v1 = bm_s[r1 + col];
            if (nt >= 6) {
                bool valid = (col < LEN);
                v0 = valid ? v0 : -1e30f;
                v1 = valid ? v1 : -1e30f;
            }
            acc[nt][e]     = fmaf(acc[nt][e],     scale, v0);
            acc[nt][e + 2] = fmaf(acc[nt][e + 2], scale, v1);
        }
    }

    // --- softmax in registers ---
    float m0 = -1e30f, m1 = -1e30f;
    #pragma unroll
    for (int nt = 0; nt < 8; nt++) {
        m0 = fmaxf(m0, fmaxf(acc[nt][0], acc[nt][1]));
        m1 = fmaxf(m1, fmaxf(acc[nt][2], acc[nt][3]));
    }
    m0 = fmaxf(m0, __shfl_xor_sync(0xffffffffu, m0, 1));
    m0 = fmaxf(m0, __shfl_xor_sync(0xffffffffu, m0, 2));
    m1 = fmaxf(m1, __shfl_xor_sync(0xffffffffu, m1, 1));
    m1 = fmaxf(m1, __shfl_xor_sync(0xffffffffu, m1, 2));
    float s0 = 0.f, s1 = 0.f;
    #pragma unroll
    for (int nt = 0; nt < 8; nt++) {
        acc[nt][0] = __expf(acc[nt][0] - m0);
        acc[nt][1] = __expf(acc[nt][1] - m0);
        acc[nt][2] = __expf(acc[nt][2] - m1);
        acc[nt][3] = __expf(acc[nt][3] - m1);
        s0 += acc[nt][0] + acc[nt][1];
        s1 += acc[nt][2] + acc[nt][3];
    }
    s0 += __shfl_xor_sync(0xffffffffu, s0, 1);
    s0 += __shfl_xor_sync(0xffffffffu, s0, 2);
    s1 += __shfl_xor_sync(0xffffffffu, s1, 1);
    s1 += __shfl_xor_sync(0xffffffffu, s1, 2);
    float i0 = 1.f / s0, i1 = 1.f / s1;

    // --- O = P V (bf16x3), P fragments built in registers ---
    float oacc[4][4];
    #pragma unroll
    for (int nt = 0; nt < 4; nt++)
        #pragma unroll
        for (int r = 0; r < 4; r++) oacc[nt][r] = 0.f;

    #pragma unroll
    for (int ks = 0; ks < 4; ks++) {
        float p00 = acc[2*ks][0]   * i0, p01 = acc[2*ks][1]   * i0;
        float p02 = acc[2*ks][2]   * i1, p03 = acc[2*ks][3]   * i1;
        float p10 = acc[2*ks+1][0] * i0, p11 = acc[2*ks+1][1] * i0;
        float p12 = acc[2*ks+1][2] * i1, p13 = acc[2*ks+1][3] * i1;

        uint32_t ph_[4], pl_[4];
        ph_[0] = pack_bf16x2(p00, p01);
        ph_[1] = pack_bf16x2(p02, p03);
        ph_[2] = pack_bf16x2(p10, p11);
        ph_[3] = pack_bf16x2(p12, p13);
        {
            __nv_bfloat162 hh;
            *(uint32_t*)&hh = ph_[0];
            pl_[0] = pack_bf16x2(p00 - __bfloat162float(hh.x), p01 - __bfloat162float(hh.y));
            *(uint32_t*)&hh = ph_[1];
            pl_[1] = pack_bf16x2(p02 - __bfloat162float(hh.x), p03 - __bfloat162float(hh.y));
            *(uint32_t*)&hh = ph_[2];
            pl_[2] = pack_bf16x2(p10 - __bfloat162float(hh.x), p11 - __bfloat162float(hh.y));
            *(uint32_t*)&hh = ph_[3];
            pl_[3] = pack_bf16x2(p12 - __bfloat162float(hh.x), p13 - __bfloat162float(hh.y));
        }

        #pragma unroll
        for (int dp = 0; dp < 2; dp++) {
            int vrow = ks * 16 + li + (g & 1) * 8;
            int vcol = dp * 16 + (g >> 1) * 8;
            uint32_t voff = (uint32_t)(vrow * AQS + vcol) * 2;
            uint32_t vh_[4], vl_[4];
            LDSM_X4_T(vh_[0], vh_[1], vh_[2], vh_[3], sb + 4 * 2560 * 2 + voff);
            LDSM_X4_T(vl_[0], vl_[1], vl_[2], vl_[3], sb + 5 * 2560 * 2 + voff);
            uint32_t bh0[2] = {vh_[0], vh_[1]}, bh1[2] = {vh_[2], vh_[3]};
            uint32_t bl0[2] = {vl_[0], vl_[1]}, bl1[2] = {vl_[2], vl_[3]};
            MMA_BF16(oacc[dp * 2],     ph_, bh0);
            MMA_BF16(oacc[dp * 2],     ph_, bl0);
            MMA_BF16(oacc[dp * 2],     pl_, bh0);
            MMA_BF16(oacc[dp * 2 + 1], ph_, bh1);
            MMA_BF16(oacc[dp * 2 + 1], ph_, bl1);
            MMA_BF16(oacc[dp * 2 + 1], pl_, bh1);
        }
    }

    // --- write O split hi/lo ---
    #pragma unroll
    for (int nt = 0; nt < 4; nt++) {
        int d = nt * 8 + (lane & 3) * 2;
        #pragma unroll
        for (int rr = 0; rr < 2; rr++) {
            int qi = (rr == 0) ? qi0 : qi1;
            if (qi < LEN) {
                float v0 = oacc[nt][rr * 2], v1 = oacc[nt][rr * 2 + 1];
                __nv_bfloat162 hh, ll;
                hh.x = __float2bfloat16(v0); hh.y = __float2bfloat16(v1);
                ll.x = __float2bfloat16(v0 - __bfloat162float(hh.x));
                ll.y = __float2bfloat16(v1 - __bfloat162float(hh.y));
                size_t off = ((size_t)b * LEN + qi) * CH + h * HDIM + d;
                *(__nv_bfloat162*)(g_ao_hi + off) = hh;
                *(__nv_bfloat162*)(g_ao_lo + off) = ll;
            }
        }
    }
}

// ---------------------------------------------------------------------------
// Launch
// ---------------------------------------------------------------------------
extern "C" void kernel_launch(void* const* d_in, const int* in_sizes, int n_in,
                              void* d_out, int out_size) {
    const float* x          = (const float*)d_in[0];
    const int*   rel_index  = (const int*)d_in[1];
    const float* attn_mask  = (const float*)d_in[2];
    const float* qkv_w      = (const float*)d_in[3];
    const float* qkv_b      = (const float*)d_in[4];
    const float* bias_table = (const float*)d_in[5];
    const float* proj_w     = (const float*)d_in[6];
    const float* proj_b     = (const float*)d_in[7];
    float* out = (float*)d_out;

    __nv_bfloat16 *qkvh, *qkvl, *xh, *xl, *aoh, *aol, *wqh, *wql, *wph, *wpl;
    cudaGetSymbolAddress((void**)&qkvh, g_qkv_hi);
    cudaGetSymbolAddress((void**)&qkvl, g_qkv_lo);
    cudaGetSymbolAddress((void**)&xh,  g_x_hi);
    cudaGetSymbolAddress((void**)&xl,  g_x_lo);
    cudaGetSymbolAddress((void**)&aoh, g_ao_hi);
    cudaGetSymbolAddress((void**)&aol, g_ao_lo);
    cudaGetSymbolAddress((void**)&wqh, g_wq_hi);
    cudaGetSymbolAddress((void**)&wql, g_wq_lo);
    cudaGetSymbolAddress((void**)&wph, g_wp_hi);
    cudaGetSymbolAddress((void**)&wpl, g_wp_lo);

    cudaFuncSetAttribute(gemm_bf16x3_kernel,
                         cudaFuncAttributeMaxDynamicSharedMemorySize,
                         GEMM_SMEM_BYTES);
    cudaFuncSetAttribute(attn_mma_kernel,
                         cudaFuncAttributeMaxDynamicSharedMemorySize,
                         ATTN_SMEM_BYTES);

    // 1) combined bias+mask table
    {
        int total = MASKW * HEADS * LEN * LEN;
        bm_kernel<<<(total + 255) / 256, 256>>>(rel_index, bias_table, attn_mask);
    }
    // 2) merged prep: x split + both weight transposes/splits
    {
        int total = XN4 + WQN + WPN;
        prep_kernel<<<(total + 255) / 256, 256>>>(x, qkv_w, proj_w);
    }
    // 3) qkv GEMM -> split bf16 output
    {
        dim3 grid(THREEC / 128, NTOK / 128);
        gemm_bf16x3_kernel<<<grid, 256, GEMM_SMEM_BYTES>>>(
            xh, xl, wqh, wql, qkv_b, nullptr, qkvh, qkvl, THREEC);
    }
    // 4) attention (single window per block, register-P, ALU-trimmed)
    {
        dim3 grid(HEADS, BATCH);
        attn_mma_kernel<<<grid, 128, ATTN_SMEM_BYTES>>>();
    }
    // 5) proj GEMM -> fp32 out
    {
        dim3 grid(CH / 128, NTOK / 128);
        gemm_bf16x3_kernel<<<grid, 256, GEMM_SMEM_BYTES>>>(
            aoh, aol, wph, wpl, proj_b, out, nullptr, nullptr, CH);
    }
}